// round 9
// baseline (speedup 1.0000x reference)
#include <cuda_runtime.h>
#include <cstdint>
#include <math.h>

#define NN 100000
#define EE 3200000
#define MAXC 4

// ---------------- scratch (device globals — no allocation allowed) ----------
__device__ float g_t1[(size_t)NN * 128];   // x @ W1_rel^T
__device__ float g_h [(size_t)NN * 128];   // x @ W1_root^T + b1, += agg, relu -> h1
__device__ float g_t2[(size_t)NN * 64];    // h1 @ W2_rel^T
__device__ float g_Wt1[128 * 256];         // [k][j]: j<128 -> W1_rel[j][k], else W1_root[j-128][k]
__device__ float g_Wt2[128 * 128];         // [k][j]: j<64  -> W2_rel[j][k], else W2_root[j-64][k]
__device__ int   g_src[EE];
__device__ int   g_dst[EE];

// ---------------- input disambiguation --------------------------------------
struct Cands {
    const float* xc[MAXC];  int nx;    // size 12,800,000
    const void*  ec[MAXC];  int ne;    // size 6,400,000
    const float* w1c[MAXC]; int n1;    // size 16,384
    const float* w2c[MAXC]; int n2;    // size 8,192
    const float* b1c[MAXC]; int nb1;   // size 128
    const float* b2c[MAXC]; int nb2;   // size 64
};

struct Sel {
    const float* x;
    const long long* ei64;
    const int* ei32;
    int is64;
    const float* W1_rel; const float* W1_root;
    const float* W2_rel; const float* W2_root;
    const float* b1; const float* b2;
};
__device__ Sel g_sel;

// varied, finite, O(1)-scale float content (rejects zeros / 0xAA poison / ints-as-floats)
__device__ bool probe_variedf(const float* p, int n) {
    if (!p) return false;
    bool varied = false; int big = 0;
    float v0 = p[0];
    for (int i = 0; i < n; i++) {
        float v = p[i];
        if (!isfinite(v) || fabsf(v) > 1e6f) return false;
        if (v != v0) varied = true;
        if (fabsf(v) > 1e-3f) big++;
    }
    return varied && big >= n / 4;
}

__device__ bool probe_edges32(const int* p) {
    bool varied = false; int v0 = p[0];
    for (int i = 0; i < 64; i++) {
        int v = p[i];
        if (v < 0 || v >= NN) return false;
        if (v != v0) varied = true;
    }
    return varied;
}

__device__ bool probe_edges64(const long long* p) {
    bool varied = false; long long v0 = p[0];
    for (int i = 0; i < 64; i++) {
        long long v = p[i];
        if (v < 0 || v >= NN) return false;
        if (v != v0) varied = true;
    }
    return varied;
}

__global__ void probe_kernel(Cands c) {
    if (threadIdx.x != 0 || blockIdx.x != 0) return;
    Sel s;
    // x: first varied candidate
    s.x = c.xc[0];
    for (int i = 0; i < c.nx; i++)
        if (probe_variedf(c.xc[i], 64)) { s.x = c.xc[i]; break; }
    // edge_index: first candidate validating as int32 (both src and dst rows), else int64
    s.is64 = 0; s.ei32 = (const int*)c.ec[0]; s.ei64 = (const long long*)c.ec[0];
    for (int i = 0; i < c.ne; i++) {
        const int* p32 = (const int*)c.ec[i];
        if (probe_edges32(p32) && probe_edges32(p32 + EE)) { s.ei32 = p32; s.is64 = 0; break; }
        const long long* p64 = (const long long*)c.ec[i];
        if (probe_edges64(p64) && probe_edges64(p64 + EE)) { s.ei64 = p64; s.is64 = 1; break; }
    }
    // W1 pair: first two varied candidates, in order (rel, root)
    s.W1_rel = nullptr; s.W1_root = nullptr;
    for (int i = 0; i < c.n1; i++)
        if (probe_variedf(c.w1c[i], 64)) {
            if (!s.W1_rel) s.W1_rel = c.w1c[i];
            else if (!s.W1_root) { s.W1_root = c.w1c[i]; break; }
        }
    if (!s.W1_rel)  s.W1_rel  = c.w1c[0];
    if (!s.W1_root) s.W1_root = c.w1c[c.n1 > 1 ? 1 : 0];
    // W2 pair
    s.W2_rel = nullptr; s.W2_root = nullptr;
    for (int i = 0; i < c.n2; i++)
        if (probe_variedf(c.w2c[i], 64)) {
            if (!s.W2_rel) s.W2_rel = c.w2c[i];
            else if (!s.W2_root) { s.W2_root = c.w2c[i]; break; }
        }
    if (!s.W2_rel)  s.W2_rel  = c.w2c[0];
    if (!s.W2_root) s.W2_root = c.w2c[c.n2 > 1 ? 1 : 0];
    // biases
    s.b1 = c.b1c[0];
    for (int i = 0; i < c.nb1; i++)
        if (probe_variedf(c.b1c[i], 64)) { s.b1 = c.b1c[i]; break; }
    s.b2 = c.b2c[0];
    for (int i = 0; i < c.nb2; i++)
        if (probe_variedf(c.b2c[i], 64)) { s.b2 = c.b2c[i]; break; }
    g_sel = s;
}

// Normalize indices to int32 g_src/g_dst.
__global__ __launch_bounds__(256) void convert_kernel() {
    int i = blockIdx.x * blockDim.x + threadIdx.x;
    if (i >= EE) return;
    if (g_sel.is64) {
        g_src[i] = (int)g_sel.ei64[i];
        g_dst[i] = (int)g_sel.ei64[i + EE];
    } else {
        g_src[i] = g_sel.ei32[i];
        g_dst[i] = g_sel.ei32[i + EE];
    }
}

__global__ void prep_kernel() {
    int i = blockIdx.x * blockDim.x + threadIdx.x;
    const float* W1_rel  = g_sel.W1_rel;
    const float* W1_root = g_sel.W1_root;
    const float* W2_rel  = g_sel.W2_rel;
    const float* W2_root = g_sel.W2_root;
    if (i < 128 * 256) {
        int k = i >> 8, j = i & 255;
        g_Wt1[i] = (j < 128) ? W1_rel[j * 128 + k] : W1_root[(j - 128) * 128 + k];
    }
    if (i < 128 * 128) {
        int k = i >> 7, j = i & 127;
        g_Wt2[i] = (j < 64) ? W2_rel[j * 128 + k] : W2_root[(j - 64) * 128 + k];
    }
}

// ---------------- GEMM ------------------------------------------------------
// C[n, CO] = A[n,128] @ Wt[128, CO]; cols < SPLIT -> outA (internal), cols >= SPLIT -> outB (+bias)
// BM=128, BN=128, BK=8, 256 threads, 8x8 micro-tile.
template <int CO, int SPLIT, bool L1>
__global__ __launch_bounds__(256) void sgemm_dual(float* __restrict__ outB_ext, int n)
{
    const float* __restrict__ A    = L1 ? g_sel.x : g_h;
    const float* __restrict__ bias = L1 ? g_sel.b1 : g_sel.b2;
    const float* __restrict__ Wt   = L1 ? g_Wt1 : g_Wt2;
    float* __restrict__ outA = L1 ? g_t1 : g_t2;
    float* __restrict__ outB = L1 ? g_h : outB_ext;

    __shared__ float As[8][128];
    __shared__ float Ws[8][128];

    const int t = threadIdx.x;
    const int rowTile = blockIdx.x * 128;
    const int colTile = blockIdx.y * 128;

    const int a_r = t >> 1;            // 0..127
    const int a_c = (t & 1) * 4;       // 0 or 4
    const int w_r = t >> 5;            // 0..7
    const int w_c = (t & 31) * 4;      // 0..124

    const int tx = t & 15, ty = t >> 4;

    float acc[8][8];
#pragma unroll
    for (int i = 0; i < 8; i++)
#pragma unroll
        for (int j = 0; j < 8; j++) acc[i][j] = 0.f;

    const int gr_a = rowTile + a_r;
    for (int k0 = 0; k0 < 128; k0 += 8) {
        float4 av = make_float4(0.f, 0.f, 0.f, 0.f);
        if (gr_a < n) av = *(const float4*)(A + (size_t)gr_a * 128 + k0 + a_c);
        As[a_c + 0][a_r] = av.x;
        As[a_c + 1][a_r] = av.y;
        As[a_c + 2][a_r] = av.z;
        As[a_c + 3][a_r] = av.w;
        *(float4*)&Ws[w_r][w_c] = *(const float4*)(Wt + (size_t)(k0 + w_r) * CO + colTile + w_c);
        __syncthreads();
#pragma unroll
        for (int kk = 0; kk < 8; kk++) {
            float a[8], b[8];
            *(float4*)&a[0] = *(float4*)&As[kk][ty * 8];
            *(float4*)&a[4] = *(float4*)&As[kk][ty * 8 + 4];
            *(float4*)&b[0] = *(float4*)&Ws[kk][tx * 8];
            *(float4*)&b[4] = *(float4*)&Ws[kk][tx * 8 + 4];
#pragma unroll
            for (int i = 0; i < 8; i++)
#pragma unroll
                for (int j = 0; j < 8; j++) acc[i][j] = fmaf(a[i], b[j], acc[i][j]);
        }
        __syncthreads();
    }

#pragma unroll
    for (int i = 0; i < 8; i++) {
        int gr = rowTile + ty * 8 + i;
        if (gr >= n) continue;
#pragma unroll
        for (int j = 0; j < 8; j++) {
            int gc = colTile + tx * 8 + j;
            float v = acc[i][j];
            if (gc < SPLIT) outA[(size_t)gr * SPLIT + gc] = v;
            else            outB[(size_t)gr * (CO - SPLIT) + (gc - SPLIT)] = v + bias[gc - SPLIT];
        }
    }
}

// ---------------- scatter / relu --------------------------------------------
// One warp per edge, 128 floats: lane covers 4 consecutive floats. Scalar atomicAdd into g_h.
__global__ __launch_bounds__(256) void scatter128_kernel() {
    int warp = (blockIdx.x * blockDim.x + threadIdx.x) >> 5;
    int lane = threadIdx.x & 31;
    if (warp >= EE) return;
    int s = __ldg(g_src + warp);
    int d = __ldg(g_dst + warp);
    float4 v = *(const float4*)(g_t1 + (size_t)s * 128 + lane * 4);
    float* p = g_h + (size_t)d * 128 + lane * 4;
    atomicAdd(p + 0, v.x);
    atomicAdd(p + 1, v.y);
    atomicAdd(p + 2, v.z);
    atomicAdd(p + 3, v.w);
}

// 16 lanes per edge, 64 floats. Scalar atomicAdd into d_out.
__global__ __launch_bounds__(256) void scatter64_kernel(float* __restrict__ out) {
    int tid = blockIdx.x * blockDim.x + threadIdx.x;
    int e = tid >> 4;
    int l = tid & 15;
    if (e >= EE) return;
    int s = __ldg(g_src + e);
    int d = __ldg(g_dst + e);
    float4 v = *(const float4*)(g_t2 + (size_t)s * 64 + l * 4);
    float* p = out + (size_t)d * 64 + l * 4;
    atomicAdd(p + 0, v.x);
    atomicAdd(p + 1, v.y);
    atomicAdd(p + 2, v.z);
    atomicAdd(p + 3, v.w);
}

__global__ __launch_bounds__(256) void relu_kernel(int n4) {
    int i = blockIdx.x * blockDim.x + threadIdx.x;
    if (i >= n4) return;
    float4 v = ((const float4*)g_h)[i];
    v.x = fmaxf(v.x, 0.f);
    v.y = fmaxf(v.y, 0.f);
    v.z = fmaxf(v.z, 0.f);
    v.w = fmaxf(v.w, 0.f);
    ((float4*)g_h)[i] = v;
}

// ---------------- launch ----------------------------------------------------
extern "C" void kernel_launch(void* const* d_in, const int* in_sizes, int n_in,
                              void* d_out, int out_size) {
    Cands c;
    c.nx = c.ne = c.n1 = c.n2 = c.nb1 = c.nb2 = 0;
    for (int i = 0; i < MAXC; i++) {
        c.xc[i] = nullptr; c.ec[i] = nullptr; c.w1c[i] = nullptr;
        c.w2c[i] = nullptr; c.b1c[i] = nullptr; c.b2c[i] = nullptr;
    }
    for (int i = 0; i < n_in; i++) {
        switch (in_sizes[i]) {
            case 12800000: if (c.nx  < MAXC) c.xc [c.nx++ ] = (const float*)d_in[i]; break;
            case 6400000:  if (c.ne  < MAXC) c.ec [c.ne++ ] = d_in[i]; break;
            case 16384:    if (c.n1  < MAXC) c.w1c[c.n1++ ] = (const float*)d_in[i]; break;
            case 8192:     if (c.n2  < MAXC) c.w2c[c.n2++ ] = (const float*)d_in[i]; break;
            case 128:      if (c.nb1 < MAXC) c.b1c[c.nb1++] = (const float*)d_in[i]; break;
            case 64:       if (c.nb2 < MAXC) c.b2c[c.nb2++] = (const float*)d_in[i]; break;
            default: break;
        }
    }
    float* out = (float*)d_out;

    // Resolve real input pointers by content (rejects zero/poison dummy buffers)
    probe_kernel<<<1, 32>>>(c);

    // Normalize edge_index into g_src/g_dst
    convert_kernel<<<(EE + 255) / 256, 256>>>();

    // Transposed / concatenated weight layouts
    prep_kernel<<<128, 256>>>();

    const int rowBlocks = (NN + 127) / 128;  // 782

    // Layer 1: t1 = x@W1_rel^T ; g_h = x@W1_root^T + b1
    sgemm_dual<256, 128, true><<<dim3(rowBlocks, 2), 256>>>(nullptr, NN);

    // g_h += segment_sum(t1[src] -> dst)
    scatter128_kernel<<<EE / 8, 256>>>();

    // h1 = relu(g_h)
    relu_kernel<<<(NN * 128 / 4 + 255) / 256, 256>>>(NN * 128 / 4);

    // Layer 2: t2 = h1@W2_rel^T ; d_out = h1@W2_root^T + b2
    sgemm_dual<128, 64, false><<<dim3(rowBlocks, 1), 256>>>(out, NN);

    // d_out += segment_sum(t2[src] -> dst)
    scatter64_kernel<<<EE / 16, 256>>>(out);
}

// round 11
// speedup vs baseline: 1.1941x; 1.1941x over previous
#include <cuda_runtime.h>
#include <cstdint>
#include <math.h>

#define NN 100000
#define EE 3200000
#define MAXC 4

// ---------------- scratch (device globals — no allocation allowed) ----------
__device__ float g_t1[(size_t)NN * 128];   // x @ W1_rel^T
__device__ float g_h [(size_t)NN * 128];   // x @ W1_root^T + b1, += agg  (pre-relu)
__device__ float g_t2[(size_t)NN * 64];    // relu(h) @ W2_rel^T
__device__ float g_Wt1[128 * 256];         // [k][j]: j<128 -> W1_rel[j][k], else W1_root[j-128][k]
__device__ float g_Wt2[128 * 128];         // [k][j]: j<64  -> W2_rel[j][k], else W2_root[j-64][k]
__device__ int   g_src[EE];
__device__ int   g_dst[EE];

// ---------------- input disambiguation --------------------------------------
struct Cands {
    const float* xc[MAXC];  int nx;    // size 12,800,000
    const void*  ec[MAXC];  int ne;    // size 6,400,000
    const float* w1c[MAXC]; int n1;    // size 16,384
    const float* w2c[MAXC]; int n2;    // size 8,192
    const float* b1c[MAXC]; int nb1;   // size 128
    const float* b2c[MAXC]; int nb2;   // size 64
};

struct Sel {
    const float* x;
    const long long* ei64;
    const int* ei32;
    int is64;
    const float* W1_rel; const float* W1_root;
    const float* W2_rel; const float* W2_root;
    const float* b1; const float* b2;
};
__device__ Sel g_sel;

// varied, finite, O(1)-scale float content (rejects zeros / 0xAA poison / ints-as-floats)
__device__ bool probe_variedf(const float* p, int n) {
    if (!p) return false;
    bool varied = false; int big = 0;
    float v0 = p[0];
    for (int i = 0; i < n; i++) {
        float v = p[i];
        if (!isfinite(v) || fabsf(v) > 1e6f) return false;
        if (v != v0) varied = true;
        if (fabsf(v) > 1e-3f) big++;
    }
    return varied && big >= n / 4;
}

__device__ bool probe_edges32(const int* p) {
    bool varied = false; int v0 = p[0];
    for (int i = 0; i < 64; i++) {
        int v = p[i];
        if (v < 0 || v >= NN) return false;
        if (v != v0) varied = true;
    }
    return varied;
}

__device__ bool probe_edges64(const long long* p) {
    bool varied = false; long long v0 = p[0];
    for (int i = 0; i < 64; i++) {
        long long v = p[i];
        if (v < 0 || v >= NN) return false;
        if (v != v0) varied = true;
    }
    return varied;
}

__global__ void probe_kernel(Cands c) {
    if (threadIdx.x != 0 || blockIdx.x != 0) return;
    Sel s;
    s.x = c.xc[0];
    for (int i = 0; i < c.nx; i++)
        if (probe_variedf(c.xc[i], 64)) { s.x = c.xc[i]; break; }
    s.is64 = 0; s.ei32 = (const int*)c.ec[0]; s.ei64 = (const long long*)c.ec[0];
    for (int i = 0; i < c.ne; i++) {
        const int* p32 = (const int*)c.ec[i];
        if (probe_edges32(p32) && probe_edges32(p32 + EE)) { s.ei32 = p32; s.is64 = 0; break; }
        const long long* p64 = (const long long*)c.ec[i];
        if (probe_edges64(p64) && probe_edges64(p64 + EE)) { s.ei64 = p64; s.is64 = 1; break; }
    }
    s.W1_rel = nullptr; s.W1_root = nullptr;
    for (int i = 0; i < c.n1; i++)
        if (probe_variedf(c.w1c[i], 64)) {
            if (!s.W1_rel) s.W1_rel = c.w1c[i];
            else if (!s.W1_root) { s.W1_root = c.w1c[i]; break; }
        }
    if (!s.W1_rel)  s.W1_rel  = c.w1c[0];
    if (!s.W1_root) s.W1_root = c.w1c[c.n1 > 1 ? 1 : 0];
    s.W2_rel = nullptr; s.W2_root = nullptr;
    for (int i = 0; i < c.n2; i++)
        if (probe_variedf(c.w2c[i], 64)) {
            if (!s.W2_rel) s.W2_rel = c.w2c[i];
            else if (!s.W2_root) { s.W2_root = c.w2c[i]; break; }
        }
    if (!s.W2_rel)  s.W2_rel  = c.w2c[0];
    if (!s.W2_root) s.W2_root = c.w2c[c.n2 > 1 ? 1 : 0];
    s.b1 = c.b1c[0];
    for (int i = 0; i < c.nb1; i++)
        if (probe_variedf(c.b1c[i], 64)) { s.b1 = c.b1c[i]; break; }
    s.b2 = c.b2c[0];
    for (int i = 0; i < c.nb2; i++)
        if (probe_variedf(c.b2c[i], 64)) { s.b2 = c.b2c[i]; break; }
    g_sel = s;
}

// Normalize indices to int32 g_src/g_dst.
__global__ __launch_bounds__(256) void convert_kernel() {
    int i = blockIdx.x * blockDim.x + threadIdx.x;
    if (i >= EE) return;
    if (g_sel.is64) {
        g_src[i] = (int)g_sel.ei64[i];
        g_dst[i] = (int)g_sel.ei64[i + EE];
    } else {
        g_src[i] = g_sel.ei32[i];
        g_dst[i] = g_sel.ei32[i + EE];
    }
}

__global__ void prep_kernel() {
    int i = blockIdx.x * blockDim.x + threadIdx.x;
    const float* W1_rel  = g_sel.W1_rel;
    const float* W1_root = g_sel.W1_root;
    const float* W2_rel  = g_sel.W2_rel;
    const float* W2_root = g_sel.W2_root;
    if (i < 128 * 256) {
        int k = i >> 8, j = i & 255;
        g_Wt1[i] = (j < 128) ? W1_rel[j * 128 + k] : W1_root[(j - 128) * 128 + k];
    }
    if (i < 128 * 128) {
        int k = i >> 7, j = i & 127;
        g_Wt2[i] = (j < 64) ? W2_rel[j * 128 + k] : W2_root[(j - 64) * 128 + k];
    }
}

// ---------------- GEMM ------------------------------------------------------
// C[n, CO] = act(A)[n,128] @ Wt[128, CO]; cols < SPLIT -> outA, cols >= SPLIT -> outB (+bias)
// BM=128, BN=128, BK=8, 256 threads, 8x8 micro-tile. L1=false applies relu to A on load.
template <int CO, int SPLIT, bool L1>
__global__ __launch_bounds__(256) void sgemm_dual(float* __restrict__ outB_ext, int n)
{
    const float* __restrict__ A    = L1 ? g_sel.x : g_h;
    const float* __restrict__ bias = L1 ? g_sel.b1 : g_sel.b2;
    const float* __restrict__ Wt   = L1 ? g_Wt1 : g_Wt2;
    float* __restrict__ outA = L1 ? g_t1 : g_t2;
    float* __restrict__ outB = L1 ? g_h : outB_ext;

    __shared__ float As[8][128];
    __shared__ float Ws[8][128];

    const int t = threadIdx.x;
    const int rowTile = blockIdx.x * 128;
    const int colTile = blockIdx.y * 128;

    const int a_r = t >> 1;            // 0..127
    const int a_c = (t & 1) * 4;       // 0 or 4
    const int w_r = t >> 5;            // 0..7
    const int w_c = (t & 31) * 4;      // 0..124

    const int tx = t & 15, ty = t >> 4;

    float acc[8][8];
#pragma unroll
    for (int i = 0; i < 8; i++)
#pragma unroll
        for (int j = 0; j < 8; j++) acc[i][j] = 0.f;

    const int gr_a = rowTile + a_r;
    for (int k0 = 0; k0 < 128; k0 += 8) {
        float4 av = make_float4(0.f, 0.f, 0.f, 0.f);
        if (gr_a < n) av = *(const float4*)(A + (size_t)gr_a * 128 + k0 + a_c);
        if (!L1) {  // fused relu on h
            av.x = fmaxf(av.x, 0.f); av.y = fmaxf(av.y, 0.f);
            av.z = fmaxf(av.z, 0.f); av.w = fmaxf(av.w, 0.f);
        }
        As[a_c + 0][a_r] = av.x;
        As[a_c + 1][a_r] = av.y;
        As[a_c + 2][a_r] = av.z;
        As[a_c + 3][a_r] = av.w;
        *(float4*)&Ws[w_r][w_c] = *(const float4*)(Wt + (size_t)(k0 + w_r) * CO + colTile + w_c);
        __syncthreads();
#pragma unroll
        for (int kk = 0; kk < 8; kk++) {
            float a[8], b[8];
            *(float4*)&a[0] = *(float4*)&As[kk][ty * 8];
            *(float4*)&a[4] = *(float4*)&As[kk][ty * 8 + 4];
            *(float4*)&b[0] = *(float4*)&Ws[kk][tx * 8];
            *(float4*)&b[4] = *(float4*)&Ws[kk][tx * 8 + 4];
#pragma unroll
            for (int i = 0; i < 8; i++)
#pragma unroll
                for (int j = 0; j < 8; j++) acc[i][j] = fmaf(a[i], b[j], acc[i][j]);
        }
        __syncthreads();
    }

#pragma unroll
    for (int i = 0; i < 8; i++) {
        int gr = rowTile + ty * 8 + i;
        if (gr >= n) continue;
#pragma unroll
        for (int j = 0; j < 8; j++) {
            int gc = colTile + tx * 8 + j;
            float v = acc[i][j];
            if (gc < SPLIT) outA[(size_t)gr * SPLIT + gc] = v;
            else            outB[(size_t)gr * (CO - SPLIT) + (gc - SPLIT)] = v + bias[gc - SPLIT];
        }
    }
}

// ---------------- scatter ----------------------------------------------------
// One warp per edge, 128 floats: lane covers 4 consecutive floats. Vector red into g_h.
__global__ __launch_bounds__(256) void scatter128_kernel() {
    int warp = (blockIdx.x * blockDim.x + threadIdx.x) >> 5;
    int lane = threadIdx.x & 31;
    if (warp >= EE) return;
    int s = __ldg(g_src + warp);
    int d = __ldg(g_dst + warp);
    float4 v = *(const float4*)(g_t1 + (size_t)s * 128 + lane * 4);
    float* p = g_h + (size_t)d * 128 + lane * 4;
    asm volatile("red.global.add.v4.f32 [%0], {%1, %2, %3, %4};"
                 :: "l"(p), "f"(v.x), "f"(v.y), "f"(v.z), "f"(v.w) : "memory");
}

// 16 lanes per edge, 64 floats. Vector red into d_out.
__global__ __launch_bounds__(256) void scatter64_kernel(float* __restrict__ out) {
    int tid = blockIdx.x * blockDim.x + threadIdx.x;
    int e = tid >> 4;
    int l = tid & 15;
    if (e >= EE) return;
    int s = __ldg(g_src + e);
    int d = __ldg(g_dst + e);
    float4 v = *(const float4*)(g_t2 + (size_t)s * 64 + l * 4);
    float* p = out + (size_t)d * 64 + l * 4;
    asm volatile("red.global.add.v4.f32 [%0], {%1, %2, %3, %4};"
                 :: "l"(p), "f"(v.x), "f"(v.y), "f"(v.z), "f"(v.w) : "memory");
}

// ---------------- launch ----------------------------------------------------
extern "C" void kernel_launch(void* const* d_in, const int* in_sizes, int n_in,
                              void* d_out, int out_size) {
    Cands c;
    c.nx = c.ne = c.n1 = c.n2 = c.nb1 = c.nb2 = 0;
    for (int i = 0; i < MAXC; i++) {
        c.xc[i] = nullptr; c.ec[i] = nullptr; c.w1c[i] = nullptr;
        c.w2c[i] = nullptr; c.b1c[i] = nullptr; c.b2c[i] = nullptr;
    }
    for (int i = 0; i < n_in; i++) {
        switch (in_sizes[i]) {
            case 12800000: if (c.nx  < MAXC) c.xc [c.nx++ ] = (const float*)d_in[i]; break;
            case 6400000:  if (c.ne  < MAXC) c.ec [c.ne++ ] = d_in[i]; break;
            case 16384:    if (c.n1  < MAXC) c.w1c[c.n1++ ] = (const float*)d_in[i]; break;
            case 8192:     if (c.n2  < MAXC) c.w2c[c.n2++ ] = (const float*)d_in[i]; break;
            case 128:      if (c.nb1 < MAXC) c.b1c[c.nb1++] = (const float*)d_in[i]; break;
            case 64:       if (c.nb2 < MAXC) c.b2c[c.nb2++] = (const float*)d_in[i]; break;
            default: break;
        }
    }
    float* out = (float*)d_out;

    // Resolve real input pointers by content (rejects zero/poison dummy buffers)
    probe_kernel<<<1, 32>>>(c);

    // Normalize edge_index into g_src/g_dst
    convert_kernel<<<(EE + 255) / 256, 256>>>();

    // Transposed / concatenated weight layouts
    prep_kernel<<<128, 256>>>();

    const int rowBlocks = (NN + 127) / 128;  // 782

    // Layer 1: t1 = x@W1_rel^T ; g_h = x@W1_root^T + b1
    sgemm_dual<256, 128, true><<<dim3(rowBlocks, 2), 256>>>(nullptr, NN);

    // g_h += segment_sum(t1[src] -> dst)
    scatter128_kernel<<<EE / 8, 256>>>();

    // Layer 2 (relu fused on A load): t2 = relu(h)@W2_rel^T ; d_out = relu(h)@W2_root^T + b2
    sgemm_dual<128, 64, false><<<dim3(rowBlocks, 1), 256>>>(out, NN);

    // d_out += segment_sum(t2[src] -> dst)
    scatter64_kernel<<<EE / 16, 256>>>(out);
}

// round 13
// speedup vs baseline: 2.2920x; 1.9194x over previous
#include <cuda_runtime.h>
#include <cstdint>
#include <math.h>

#define NN 100000
#define EE 3200000
#define MAXC 4

// ---------------- scratch (device globals — no allocation allowed) ----------
__device__ float g_t1[(size_t)NN * 128];   // x @ W1_rel^T
__device__ float g_h [(size_t)NN * 128];   // x@W1_root^T + b1, += agg, relu
__device__ float g_t2[(size_t)NN * 64];    // relu(h) @ W2_rel^T
__device__ float g_Wt1[128 * 256];
__device__ float g_Wt2[128 * 128];
__device__ int   g_src[EE];
__device__ int   g_dst[EE];
// CSR (dst-sorted)
__device__ int   g_cnt[NN];
__device__ int   g_cur[NN];
__device__ int   g_off[NN + 1];
__device__ int   g_eidx[EE];               // src indices grouped by dst

// ---------------- input disambiguation --------------------------------------
struct Cands {
    const float* xc[MAXC];  int nx;
    const void*  ec[MAXC];  int ne;
    const float* w1c[MAXC]; int n1;
    const float* w2c[MAXC]; int n2;
    const float* b1c[MAXC]; int nb1;
    const float* b2c[MAXC]; int nb2;
};
struct Sel {
    const float* x;
    const long long* ei64;
    const int* ei32;
    int is64;
    const float* W1_rel; const float* W1_root;
    const float* W2_rel; const float* W2_root;
    const float* b1; const float* b2;
};
__device__ Sel g_sel;

__device__ bool probe_variedf(const float* p, int n) {
    if (!p) return false;
    bool varied = false; int big = 0;
    float v0 = p[0];
    for (int i = 0; i < n; i++) {
        float v = p[i];
        if (!isfinite(v) || fabsf(v) > 1e6f) return false;
        if (v != v0) varied = true;
        if (fabsf(v) > 1e-3f) big++;
    }
    return varied && big >= n / 4;
}
__device__ bool probe_edges32(const int* p) {
    bool varied = false; int v0 = p[0];
    for (int i = 0; i < 64; i++) {
        int v = p[i];
        if (v < 0 || v >= NN) return false;
        if (v != v0) varied = true;
    }
    return varied;
}
__device__ bool probe_edges64(const long long* p) {
    bool varied = false; long long v0 = p[0];
    for (int i = 0; i < 64; i++) {
        long long v = p[i];
        if (v < 0 || v >= NN) return false;
        if (v != v0) varied = true;
    }
    return varied;
}

__global__ void probe_kernel(Cands c) {
    if (threadIdx.x != 0 || blockIdx.x != 0) return;
    Sel s;
    s.x = c.xc[0];
    for (int i = 0; i < c.nx; i++)
        if (probe_variedf(c.xc[i], 64)) { s.x = c.xc[i]; break; }
    s.is64 = 0; s.ei32 = (const int*)c.ec[0]; s.ei64 = (const long long*)c.ec[0];
    for (int i = 0; i < c.ne; i++) {
        const int* p32 = (const int*)c.ec[i];
        if (probe_edges32(p32) && probe_edges32(p32 + EE)) { s.ei32 = p32; s.is64 = 0; break; }
        const long long* p64 = (const long long*)c.ec[i];
        if (probe_edges64(p64) && probe_edges64(p64 + EE)) { s.ei64 = p64; s.is64 = 1; break; }
    }
    s.W1_rel = nullptr; s.W1_root = nullptr;
    for (int i = 0; i < c.n1; i++)
        if (probe_variedf(c.w1c[i], 64)) {
            if (!s.W1_rel) s.W1_rel = c.w1c[i];
            else if (!s.W1_root) { s.W1_root = c.w1c[i]; break; }
        }
    if (!s.W1_rel)  s.W1_rel  = c.w1c[0];
    if (!s.W1_root) s.W1_root = c.w1c[c.n1 > 1 ? 1 : 0];
    s.W2_rel = nullptr; s.W2_root = nullptr;
    for (int i = 0; i < c.n2; i++)
        if (probe_variedf(c.w2c[i], 64)) {
            if (!s.W2_rel) s.W2_rel = c.w2c[i];
            else if (!s.W2_root) { s.W2_root = c.w2c[i]; break; }
        }
    if (!s.W2_rel)  s.W2_rel  = c.w2c[0];
    if (!s.W2_root) s.W2_root = c.w2c[c.n2 > 1 ? 1 : 0];
    s.b1 = c.b1c[0];
    for (int i = 0; i < c.nb1; i++)
        if (probe_variedf(c.b1c[i], 64)) { s.b1 = c.b1c[i]; break; }
    s.b2 = c.b2c[0];
    for (int i = 0; i < c.nb2; i++)
        if (probe_variedf(c.b2c[i], 64)) { s.b2 = c.b2c[i]; break; }
    g_sel = s;
}

// Zero CSR counters (MUST complete before convert_kernel's histogram).
__global__ __launch_bounds__(256) void zero_kernel() {
    int i = blockIdx.x * blockDim.x + threadIdx.x;
    if (i < NN) { g_cnt[i] = 0; g_cur[i] = 0; }
}

// Normalize indices + build count histogram.
__global__ __launch_bounds__(256) void convert_kernel() {
    int i = blockIdx.x * blockDim.x + threadIdx.x;
    if (i >= EE) return;
    int s, d;
    if (g_sel.is64) { s = (int)g_sel.ei64[i]; d = (int)g_sel.ei64[i + EE]; }
    else            { s = g_sel.ei32[i];      d = g_sel.ei32[i + EE]; }
    g_src[i] = s;
    g_dst[i] = d;
    atomicAdd(&g_cnt[d], 1);
}

// Single-block exclusive scan of g_cnt -> g_off (100k elements, 1024 threads).
__global__ __launch_bounds__(1024) void scan_kernel() {
    __shared__ int sdata[1024];
    __shared__ int s_carry;
    int t = threadIdx.x;
    if (t == 0) s_carry = 0;
    __syncthreads();
    for (int base = 0; base < NN; base += 1024) {
        int idx = base + t;
        int v = (idx < NN) ? g_cnt[idx] : 0;
        sdata[t] = v;
        __syncthreads();
        for (int off = 1; off < 1024; off <<= 1) {
            int tmp = (t >= off) ? sdata[t - off] : 0;
            __syncthreads();
            sdata[t] += tmp;
            __syncthreads();
        }
        if (idx < NN) g_off[idx] = s_carry + sdata[t] - v;
        __syncthreads();
        if (t == 1023) s_carry += sdata[1023];
        __syncthreads();
    }
    if (t == 0) g_off[NN] = s_carry;
}

__global__ __launch_bounds__(256) void fill_kernel() {
    int e = blockIdx.x * blockDim.x + threadIdx.x;
    if (e >= EE) return;
    int d = g_dst[e];
    int pos = atomicAdd(&g_cur[d], 1);
    g_eidx[g_off[d] + pos] = g_src[e];
}

__global__ void prep_kernel() {
    int i = blockIdx.x * blockDim.x + threadIdx.x;
    const float* W1_rel  = g_sel.W1_rel;
    const float* W1_root = g_sel.W1_root;
    const float* W2_rel  = g_sel.W2_rel;
    const float* W2_root = g_sel.W2_root;
    if (i < 128 * 256) {
        int k = i >> 8, j = i & 255;
        g_Wt1[i] = (j < 128) ? W1_rel[j * 128 + k] : W1_root[(j - 128) * 128 + k];
    }
    if (i < 128 * 128) {
        int k = i >> 7, j = i & 127;
        g_Wt2[i] = (j < 64) ? W2_rel[j * 128 + k] : W2_root[(j - 64) * 128 + k];
    }
}

// ---------------- GEMM ------------------------------------------------------
template <int CO, int SPLIT, bool L1>
__global__ __launch_bounds__(256) void sgemm_dual(float* __restrict__ outB_ext, int n)
{
    const float* __restrict__ A    = L1 ? g_sel.x : g_h;   // g_h already relu'd
    const float* __restrict__ bias = L1 ? g_sel.b1 : g_sel.b2;
    const float* __restrict__ Wt   = L1 ? g_Wt1 : g_Wt2;
    float* __restrict__ outA = L1 ? g_t1 : g_t2;
    float* __restrict__ outB = L1 ? g_h : outB_ext;

    __shared__ float As[8][128];
    __shared__ float Ws[8][128];

    const int t = threadIdx.x;
    const int rowTile = blockIdx.x * 128;
    const int colTile = blockIdx.y * 128;

    const int a_r = t >> 1;
    const int a_c = (t & 1) * 4;
    const int w_r = t >> 5;
    const int w_c = (t & 31) * 4;
    const int tx = t & 15, ty = t >> 4;

    float acc[8][8];
#pragma unroll
    for (int i = 0; i < 8; i++)
#pragma unroll
        for (int j = 0; j < 8; j++) acc[i][j] = 0.f;

    const int gr_a = rowTile + a_r;
    for (int k0 = 0; k0 < 128; k0 += 8) {
        float4 av = make_float4(0.f, 0.f, 0.f, 0.f);
        if (gr_a < n) av = *(const float4*)(A + (size_t)gr_a * 128 + k0 + a_c);
        As[a_c + 0][a_r] = av.x;
        As[a_c + 1][a_r] = av.y;
        As[a_c + 2][a_r] = av.z;
        As[a_c + 3][a_r] = av.w;
        *(float4*)&Ws[w_r][w_c] = *(const float4*)(Wt + (size_t)(k0 + w_r) * CO + colTile + w_c);
        __syncthreads();
#pragma unroll
        for (int kk = 0; kk < 8; kk++) {
            float a[8], b[8];
            *(float4*)&a[0] = *(float4*)&As[kk][ty * 8];
            *(float4*)&a[4] = *(float4*)&As[kk][ty * 8 + 4];
            *(float4*)&b[0] = *(float4*)&Ws[kk][tx * 8];
            *(float4*)&b[4] = *(float4*)&Ws[kk][tx * 8 + 4];
#pragma unroll
            for (int i = 0; i < 8; i++)
#pragma unroll
                for (int j = 0; j < 8; j++) acc[i][j] = fmaf(a[i], b[j], acc[i][j]);
        }
        __syncthreads();
    }

#pragma unroll
    for (int i = 0; i < 8; i++) {
        int gr = rowTile + ty * 8 + i;
        if (gr >= n) continue;
#pragma unroll
        for (int j = 0; j < 8; j++) {
            int gc = colTile + tx * 8 + j;
            float v = acc[i][j];
            if (gc < SPLIT) outA[(size_t)gr * SPLIT + gc] = v;
            else            outB[(size_t)gr * (CO - SPLIT) + (gc - SPLIT)] = v + bias[gc - SPLIT];
        }
    }
}

// ---------------- gather aggregation (CSR) -----------------------------------
// Warp per node, 128 floats: lane owns 4 consecutive columns. relu fused on write.
__global__ __launch_bounds__(256) void gather128_kernel() {
    int node = (blockIdx.x * blockDim.x + threadIdx.x) >> 5;
    int lane = threadIdx.x & 31;
    if (node >= NN) return;
    int beg = __ldg(g_off + node), end = __ldg(g_off + node + 1);
    float* row = g_h + (size_t)node * 128 + lane * 4;
    float4 acc = *(float4*)row;
    int e = beg;
    for (; e + 1 < end; e += 2) {
        int s0 = __ldg(g_eidx + e);
        int s1 = __ldg(g_eidx + e + 1);
        float4 v0 = *(const float4*)(g_t1 + (size_t)s0 * 128 + lane * 4);
        float4 v1 = *(const float4*)(g_t1 + (size_t)s1 * 128 + lane * 4);
        acc.x += v0.x + v1.x; acc.y += v0.y + v1.y;
        acc.z += v0.z + v1.z; acc.w += v0.w + v1.w;
    }
    if (e < end) {
        int s0 = __ldg(g_eidx + e);
        float4 v0 = *(const float4*)(g_t1 + (size_t)s0 * 128 + lane * 4);
        acc.x += v0.x; acc.y += v0.y; acc.z += v0.z; acc.w += v0.w;
    }
    acc.x = fmaxf(acc.x, 0.f); acc.y = fmaxf(acc.y, 0.f);
    acc.z = fmaxf(acc.z, 0.f); acc.w = fmaxf(acc.w, 0.f);
    *(float4*)row = acc;
}

// Warp per node, 64 floats: lane owns 2 consecutive columns. Accumulates into out.
__global__ __launch_bounds__(256) void gather64_kernel(float* __restrict__ out) {
    int node = (blockIdx.x * blockDim.x + threadIdx.x) >> 5;
    int lane = threadIdx.x & 31;
    if (node >= NN) return;
    int beg = __ldg(g_off + node), end = __ldg(g_off + node + 1);
    float* row = out + (size_t)node * 64 + lane * 2;
    float2 acc = *(float2*)row;
    int e = beg;
    for (; e + 1 < end; e += 2) {
        int s0 = __ldg(g_eidx + e);
        int s1 = __ldg(g_eidx + e + 1);
        float2 v0 = *(const float2*)(g_t2 + (size_t)s0 * 64 + lane * 2);
        float2 v1 = *(const float2*)(g_t2 + (size_t)s1 * 64 + lane * 2);
        acc.x += v0.x + v1.x; acc.y += v0.y + v1.y;
    }
    if (e < end) {
        int s0 = __ldg(g_eidx + e);
        float2 v0 = *(const float2*)(g_t2 + (size_t)s0 * 64 + lane * 2);
        acc.x += v0.x; acc.y += v0.y;
    }
    *(float2*)row = acc;
}

// ---------------- launch ----------------------------------------------------
extern "C" void kernel_launch(void* const* d_in, const int* in_sizes, int n_in,
                              void* d_out, int out_size) {
    Cands c;
    c.nx = c.ne = c.n1 = c.n2 = c.nb1 = c.nb2 = 0;
    for (int i = 0; i < MAXC; i++) {
        c.xc[i] = nullptr; c.ec[i] = nullptr; c.w1c[i] = nullptr;
        c.w2c[i] = nullptr; c.b1c[i] = nullptr; c.b2c[i] = nullptr;
    }
    for (int i = 0; i < n_in; i++) {
        switch (in_sizes[i]) {
            case 12800000: if (c.nx  < MAXC) c.xc [c.nx++ ] = (const float*)d_in[i]; break;
            case 6400000:  if (c.ne  < MAXC) c.ec [c.ne++ ] = d_in[i]; break;
            case 16384:    if (c.n1  < MAXC) c.w1c[c.n1++ ] = (const float*)d_in[i]; break;
            case 8192:     if (c.n2  < MAXC) c.w2c[c.n2++ ] = (const float*)d_in[i]; break;
            case 128:      if (c.nb1 < MAXC) c.b1c[c.nb1++] = (const float*)d_in[i]; break;
            case 64:       if (c.nb2 < MAXC) c.b2c[c.nb2++] = (const float*)d_in[i]; break;
            default: break;
        }
    }
    float* out = (float*)d_out;

    probe_kernel<<<1, 32>>>(c);
    zero_kernel<<<(NN + 255) / 256, 256>>>();          // counters = 0 (ordered before histogram!)
    convert_kernel<<<(EE + 255) / 256, 256>>>();       // indices + count histogram
    scan_kernel<<<1, 1024>>>();                        // offsets
    fill_kernel<<<(EE + 255) / 256, 256>>>();          // CSR adjacency
    prep_kernel<<<128, 256>>>();                       // weight transposes

    const int rowBlocks = (NN + 127) / 128;

    // Layer 1: t1 = x@W1_rel^T ; g_h = x@W1_root^T + b1
    sgemm_dual<256, 128, true><<<dim3(rowBlocks, 2), 256>>>(nullptr, NN);

    // g_h = relu(g_h + gather(t1))
    gather128_kernel<<<(NN * 32 + 255) / 256, 256>>>();

    // Layer 2: t2 = h@W2_rel^T ; d_out = h@W2_root^T + b2
    sgemm_dual<128, 64, false><<<dim3(rowBlocks, 1), 256>>>(out, NN);

    // d_out += gather(t2)
    gather64_kernel<<<(NN * 32 + 255) / 256, 256>>>(out);
}

// round 14
// speedup vs baseline: 2.7436x; 1.1970x over previous
#include <cuda_runtime.h>
#include <cstdint>
#include <math.h>

#define NN 100000
#define EE 3200000
#define MAXC 4
#define SCAN_BLKS ((NN + 1023) / 1024)   // 98

// ---------------- scratch (device globals — no allocation allowed) ----------
__device__ float g_t1[(size_t)NN * 128];   // x @ W1_rel^T
__device__ float g_h [(size_t)NN * 128];   // x@W1_root^T + b1, += agg, relu
__device__ float g_t2[(size_t)NN * 64];    // relu(h) @ W2_rel^T
__device__ float g_Wt1[128 * 256];
__device__ float g_Wt2[128 * 128];
__device__ int   g_src[EE];
__device__ int   g_dst[EE];
// CSR (dst-sorted)
__device__ int   g_cnt[NN];
__device__ int   g_cur[NN];
__device__ int   g_off[NN + 1];
__device__ int   g_eidx[EE];               // src indices grouped by dst
__device__ int   g_bsum[SCAN_BLKS];
__device__ int   g_boff[SCAN_BLKS];

// ---------------- input disambiguation --------------------------------------
struct Cands {
    const float* xc[MAXC];  int nx;
    const void*  ec[MAXC];  int ne;
    const float* w1c[MAXC]; int n1;
    const float* w2c[MAXC]; int n2;
    const float* b1c[MAXC]; int nb1;
    const float* b2c[MAXC]; int nb2;
};
struct Sel {
    const float* x;
    const long long* ei64;
    const int* ei32;
    int is64;
    const float* W1_rel; const float* W1_root;
    const float* W2_rel; const float* W2_root;
    const float* b1; const float* b2;
};
__device__ Sel g_sel;

__device__ bool probe_variedf(const float* p, int n) {
    if (!p) return false;
    bool varied = false; int big = 0;
    float v0 = p[0];
    for (int i = 0; i < n; i++) {
        float v = p[i];
        if (!isfinite(v) || fabsf(v) > 1e6f) return false;
        if (v != v0) varied = true;
        if (fabsf(v) > 1e-3f) big++;
    }
    return varied && big >= n / 4;
}
__device__ bool probe_edges32(const int* p) {
    bool varied = false; int v0 = p[0];
    for (int i = 0; i < 64; i++) {
        int v = p[i];
        if (v < 0 || v >= NN) return false;
        if (v != v0) varied = true;
    }
    return varied;
}
__device__ bool probe_edges64(const long long* p) {
    bool varied = false; long long v0 = p[0];
    for (int i = 0; i < 64; i++) {
        long long v = p[i];
        if (v < 0 || v >= NN) return false;
        if (v != v0) varied = true;
    }
    return varied;
}

__global__ void probe_kernel(Cands c) {
    if (threadIdx.x != 0 || blockIdx.x != 0) return;
    Sel s;
    s.x = c.xc[0];
    for (int i = 0; i < c.nx; i++)
        if (probe_variedf(c.xc[i], 64)) { s.x = c.xc[i]; break; }
    s.is64 = 0; s.ei32 = (const int*)c.ec[0]; s.ei64 = (const long long*)c.ec[0];
    for (int i = 0; i < c.ne; i++) {
        const int* p32 = (const int*)c.ec[i];
        if (probe_edges32(p32) && probe_edges32(p32 + EE)) { s.ei32 = p32; s.is64 = 0; break; }
        const long long* p64 = (const long long*)c.ec[i];
        if (probe_edges64(p64) && probe_edges64(p64 + EE)) { s.ei64 = p64; s.is64 = 1; break; }
    }
    s.W1_rel = nullptr; s.W1_root = nullptr;
    for (int i = 0; i < c.n1; i++)
        if (probe_variedf(c.w1c[i], 64)) {
            if (!s.W1_rel) s.W1_rel = c.w1c[i];
            else if (!s.W1_root) { s.W1_root = c.w1c[i]; break; }
        }
    if (!s.W1_rel)  s.W1_rel  = c.w1c[0];
    if (!s.W1_root) s.W1_root = c.w1c[c.n1 > 1 ? 1 : 0];
    s.W2_rel = nullptr; s.W2_root = nullptr;
    for (int i = 0; i < c.n2; i++)
        if (probe_variedf(c.w2c[i], 64)) {
            if (!s.W2_rel) s.W2_rel = c.w2c[i];
            else if (!s.W2_root) { s.W2_root = c.w2c[i]; break; }
        }
    if (!s.W2_rel)  s.W2_rel  = c.w2c[0];
    if (!s.W2_root) s.W2_root = c.w2c[c.n2 > 1 ? 1 : 0];
    s.b1 = c.b1c[0];
    for (int i = 0; i < c.nb1; i++)
        if (probe_variedf(c.b1c[i], 64)) { s.b1 = c.b1c[i]; break; }
    s.b2 = c.b2c[0];
    for (int i = 0; i < c.nb2; i++)
        if (probe_variedf(c.b2c[i], 64)) { s.b2 = c.b2c[i]; break; }
    g_sel = s;
}

// Zero CSR counters (MUST complete before convert_kernel's histogram).
__global__ __launch_bounds__(256) void zero_kernel() {
    int i = blockIdx.x * blockDim.x + threadIdx.x;
    if (i < NN) { g_cnt[i] = 0; g_cur[i] = 0; }
}

// Normalize indices + build count histogram.
__global__ __launch_bounds__(256) void convert_kernel() {
    int i = blockIdx.x * blockDim.x + threadIdx.x;
    if (i >= EE) return;
    int s, d;
    if (g_sel.is64) { s = (int)g_sel.ei64[i]; d = (int)g_sel.ei64[i + EE]; }
    else            { s = g_sel.ei32[i];      d = g_sel.ei32[i + EE]; }
    g_src[i] = s;
    g_dst[i] = d;
    atomicAdd(&g_cnt[d], 1);
}

// ---- 3-phase exclusive scan of g_cnt -> g_off -------------------------------
// Phase 1: per-block (1024) warp-shuffle scan; block total -> g_bsum.
__global__ __launch_bounds__(1024) void scan1_kernel() {
    __shared__ int warpsum[32];
    int b = blockIdx.x, t = threadIdx.x;
    int idx = b * 1024 + t;
    int v = (idx < NN) ? g_cnt[idx] : 0;
    int x = v;
#pragma unroll
    for (int o = 1; o < 32; o <<= 1) {
        int y = __shfl_up_sync(0xFFFFFFFFu, x, o);
        if ((t & 31) >= o) x += y;
    }
    if ((t & 31) == 31) warpsum[t >> 5] = x;
    __syncthreads();
    if (t < 32) {
        int w = warpsum[t];
#pragma unroll
        for (int o = 1; o < 32; o <<= 1) {
            int y = __shfl_up_sync(0xFFFFFFFFu, w, o);
            if (t >= o) w += y;
        }
        warpsum[t] = w;
    }
    __syncthreads();
    int ex = x - v + ((t >= 32) ? warpsum[(t >> 5) - 1] : 0);
    if (idx < NN) g_off[idx] = ex;
    if (t == 1023) g_bsum[b] = ex + v;
}

// Phase 2: serial scan of 98 block sums (one thread; trivial).
__global__ void scan2_kernel() {
    if (threadIdx.x != 0) return;
    int acc = 0;
    for (int i = 0; i < SCAN_BLKS; i++) { g_boff[i] = acc; acc += g_bsum[i]; }
    g_off[NN] = acc;
}

// Phase 3: add block offsets.
__global__ __launch_bounds__(256) void scan3_kernel() {
    int i = blockIdx.x * blockDim.x + threadIdx.x;
    if (i < NN) g_off[i] += g_boff[i >> 10];
}

__global__ __launch_bounds__(256) void fill_kernel() {
    int e = blockIdx.x * blockDim.x + threadIdx.x;
    if (e >= EE) return;
    int d = g_dst[e];
    int pos = atomicAdd(&g_cur[d], 1);
    g_eidx[g_off[d] + pos] = g_src[e];
}

__global__ void prep_kernel() {
    int i = blockIdx.x * blockDim.x + threadIdx.x;
    const float* W1_rel  = g_sel.W1_rel;
    const float* W1_root = g_sel.W1_root;
    const float* W2_rel  = g_sel.W2_rel;
    const float* W2_root = g_sel.W2_root;
    if (i < 128 * 256) {
        int k = i >> 8, j = i & 255;
        g_Wt1[i] = (j < 128) ? W1_rel[j * 128 + k] : W1_root[(j - 128) * 128 + k];
    }
    if (i < 128 * 128) {
        int k = i >> 7, j = i & 127;
        g_Wt2[i] = (j < 64) ? W2_rel[j * 128 + k] : W2_root[(j - 64) * 128 + k];
    }
}

// ---------------- GEMM ------------------------------------------------------
template <int CO, int SPLIT, bool L1>
__global__ __launch_bounds__(256) void sgemm_dual(float* __restrict__ outB_ext, int n)
{
    const float* __restrict__ A    = L1 ? g_sel.x : g_h;   // g_h already relu'd
    const float* __restrict__ bias = L1 ? g_sel.b1 : g_sel.b2;
    const float* __restrict__ Wt   = L1 ? g_Wt1 : g_Wt2;
    float* __restrict__ outA = L1 ? g_t1 : g_t2;
    float* __restrict__ outB = L1 ? g_h : outB_ext;

    __shared__ float As[8][128];
    __shared__ float Ws[8][128];

    const int t = threadIdx.x;
    const int rowTile = blockIdx.x * 128;
    const int colTile = blockIdx.y * 128;

    const int a_r = t >> 1;
    const int a_c = (t & 1) * 4;
    const int w_r = t >> 5;
    const int w_c = (t & 31) * 4;
    const int tx = t & 15, ty = t >> 4;

    float acc[8][8];
#pragma unroll
    for (int i = 0; i < 8; i++)
#pragma unroll
        for (int j = 0; j < 8; j++) acc[i][j] = 0.f;

    const int gr_a = rowTile + a_r;
    for (int k0 = 0; k0 < 128; k0 += 8) {
        float4 av = make_float4(0.f, 0.f, 0.f, 0.f);
        if (gr_a < n) av = *(const float4*)(A + (size_t)gr_a * 128 + k0 + a_c);
        As[a_c + 0][a_r] = av.x;
        As[a_c + 1][a_r] = av.y;
        As[a_c + 2][a_r] = av.z;
        As[a_c + 3][a_r] = av.w;
        *(float4*)&Ws[w_r][w_c] = *(const float4*)(Wt + (size_t)(k0 + w_r) * CO + colTile + w_c);
        __syncthreads();
#pragma unroll
        for (int kk = 0; kk < 8; kk++) {
            float a[8], b[8];
            *(float4*)&a[0] = *(float4*)&As[kk][ty * 8];
            *(float4*)&a[4] = *(float4*)&As[kk][ty * 8 + 4];
            *(float4*)&b[0] = *(float4*)&Ws[kk][tx * 8];
            *(float4*)&b[4] = *(float4*)&Ws[kk][tx * 8 + 4];
#pragma unroll
            for (int i = 0; i < 8; i++)
#pragma unroll
                for (int j = 0; j < 8; j++) acc[i][j] = fmaf(a[i], b[j], acc[i][j]);
        }
        __syncthreads();
    }

#pragma unroll
    for (int i = 0; i < 8; i++) {
        int gr = rowTile + ty * 8 + i;
        if (gr >= n) continue;
#pragma unroll
        for (int j = 0; j < 8; j++) {
            int gc = colTile + tx * 8 + j;
            float v = acc[i][j];
            if (gc < SPLIT) outA[(size_t)gr * SPLIT + gc] = v;
            else            outB[(size_t)gr * (CO - SPLIT) + (gc - SPLIT)] = v + bias[gc - SPLIT];
        }
    }
}

// ---------------- gather aggregation (CSR) -----------------------------------
__global__ __launch_bounds__(256) void gather128_kernel() {
    int node = (blockIdx.x * blockDim.x + threadIdx.x) >> 5;
    int lane = threadIdx.x & 31;
    if (node >= NN) return;
    int beg = __ldg(g_off + node), end = __ldg(g_off + node + 1);
    float* row = g_h + (size_t)node * 128 + lane * 4;
    float4 acc = *(float4*)row;
    int e = beg;
    for (; e + 1 < end; e += 2) {
        int s0 = __ldg(g_eidx + e);
        int s1 = __ldg(g_eidx + e + 1);
        float4 v0 = *(const float4*)(g_t1 + (size_t)s0 * 128 + lane * 4);
        float4 v1 = *(const float4*)(g_t1 + (size_t)s1 * 128 + lane * 4);
        acc.x += v0.x + v1.x; acc.y += v0.y + v1.y;
        acc.z += v0.z + v1.z; acc.w += v0.w + v1.w;
    }
    if (e < end) {
        int s0 = __ldg(g_eidx + e);
        float4 v0 = *(const float4*)(g_t1 + (size_t)s0 * 128 + lane * 4);
        acc.x += v0.x; acc.y += v0.y; acc.z += v0.z; acc.w += v0.w;
    }
    acc.x = fmaxf(acc.x, 0.f); acc.y = fmaxf(acc.y, 0.f);
    acc.z = fmaxf(acc.z, 0.f); acc.w = fmaxf(acc.w, 0.f);
    *(float4*)row = acc;
}

__global__ __launch_bounds__(256) void gather64_kernel(float* __restrict__ out) {
    int node = (blockIdx.x * blockDim.x + threadIdx.x) >> 5;
    int lane = threadIdx.x & 31;
    if (node >= NN) return;
    int beg = __ldg(g_off + node), end = __ldg(g_off + node + 1);
    float* row = out + (size_t)node * 64 + lane * 2;
    float2 acc = *(float2*)row;
    int e = beg;
    for (; e + 1 < end; e += 2) {
        int s0 = __ldg(g_eidx + e);
        int s1 = __ldg(g_eidx + e + 1);
        float2 v0 = *(const float2*)(g_t2 + (size_t)s0 * 64 + lane * 2);
        float2 v1 = *(const float2*)(g_t2 + (size_t)s1 * 64 + lane * 2);
        acc.x += v0.x + v1.x; acc.y += v0.y + v1.y;
    }
    if (e < end) {
        int s0 = __ldg(g_eidx + e);
        float2 v0 = *(const float2*)(g_t2 + (size_t)s0 * 64 + lane * 2);
        acc.x += v0.x; acc.y += v0.y;
    }
    *(float2*)row = acc;
}

// ---------------- launch ----------------------------------------------------
extern "C" void kernel_launch(void* const* d_in, const int* in_sizes, int n_in,
                              void* d_out, int out_size) {
    Cands c;
    c.nx = c.ne = c.n1 = c.n2 = c.nb1 = c.nb2 = 0;
    for (int i = 0; i < MAXC; i++) {
        c.xc[i] = nullptr; c.ec[i] = nullptr; c.w1c[i] = nullptr;
        c.w2c[i] = nullptr; c.b1c[i] = nullptr; c.b2c[i] = nullptr;
    }
    for (int i = 0; i < n_in; i++) {
        switch (in_sizes[i]) {
            case 12800000: if (c.nx  < MAXC) c.xc [c.nx++ ] = (const float*)d_in[i]; break;
            case 6400000:  if (c.ne  < MAXC) c.ec [c.ne++ ] = d_in[i]; break;
            case 16384:    if (c.n1  < MAXC) c.w1c[c.n1++ ] = (const float*)d_in[i]; break;
            case 8192:     if (c.n2  < MAXC) c.w2c[c.n2++ ] = (const float*)d_in[i]; break;
            case 128:      if (c.nb1 < MAXC) c.b1c[c.nb1++] = (const float*)d_in[i]; break;
            case 64:       if (c.nb2 < MAXC) c.b2c[c.nb2++] = (const float*)d_in[i]; break;
            default: break;
        }
    }
    float* out = (float*)d_out;

    probe_kernel<<<1, 32>>>(c);
    zero_kernel<<<(NN + 255) / 256, 256>>>();
    convert_kernel<<<(EE + 255) / 256, 256>>>();
    scan1_kernel<<<SCAN_BLKS, 1024>>>();
    scan2_kernel<<<1, 32>>>();
    scan3_kernel<<<(NN + 255) / 256, 256>>>();
    fill_kernel<<<(EE + 255) / 256, 256>>>();
    prep_kernel<<<128, 256>>>();

    const int rowBlocks = (NN + 127) / 128;

    // Layer 1: t1 = x@W1_rel^T ; g_h = x@W1_root^T + b1
    sgemm_dual<256, 128, true><<<dim3(rowBlocks, 2), 256>>>(nullptr, NN);

    // g_h = relu(g_h + gather(t1))
    gather128_kernel<<<(NN * 32 + 255) / 256, 256>>>();

    // Layer 2: t2 = h@W2_rel^T ; d_out = h@W2_root^T + b2
    sgemm_dual<128, 64, false><<<dim3(rowBlocks, 1), 256>>>(out, NN);

    // d_out += gather(t2)
    gather64_kernel<<<(NN * 32 + 255) / 256, 256>>>(out);
}

// round 15
// speedup vs baseline: 2.8974x; 1.0561x over previous
#include <cuda_runtime.h>
#include <cstdint>
#include <math.h>

#define NN 100000
#define EE 3200000
#define MAXC 4
#define SCAN_BLKS ((NN + 1023) / 1024)   // 98

// ---------------- scratch (device globals — no allocation allowed) ----------
__device__ float g_t1[(size_t)NN * 128];   // x @ W1_rel^T
__device__ float g_h [(size_t)NN * 128];   // x@W1_root^T + b1, += agg, relu
__device__ float g_t2[(size_t)NN * 64];    // relu(h) @ W2_rel^T
__device__ float g_Wt1[128 * 256];
__device__ float g_Wt2[128 * 128];
// CSR (dst-sorted)
__device__ int   g_cnt[NN];
__device__ int   g_cur[NN];
__device__ int   g_off[NN + 1];
__device__ int   g_eidx[EE];               // src indices grouped by dst
__device__ int   g_bsum[SCAN_BLKS];
__device__ int   g_boff[SCAN_BLKS];

// ---------------- input disambiguation --------------------------------------
struct Cands {
    const float* xc[MAXC];  int nx;
    const void*  ec[MAXC];  int ne;
    const float* w1c[MAXC]; int n1;
    const float* w2c[MAXC]; int n2;
    const float* b1c[MAXC]; int nb1;
    const float* b2c[MAXC]; int nb2;
};
struct Sel {
    const float* x;
    const long long* ei64;
    const int* ei32;
    int is64;
    const float* W1_rel; const float* W1_root;
    const float* W2_rel; const float* W2_root;
    const float* b1; const float* b2;
};
__device__ Sel g_sel;

__device__ bool probe_variedf(const float* p, int n) {
    if (!p) return false;
    bool varied = false; int big = 0;
    float v0 = p[0];
    for (int i = 0; i < n; i++) {
        float v = p[i];
        if (!isfinite(v) || fabsf(v) > 1e6f) return false;
        if (v != v0) varied = true;
        if (fabsf(v) > 1e-3f) big++;
    }
    return varied && big >= n / 4;
}
__device__ bool probe_edges32(const int* p) {
    bool varied = false; int v0 = p[0];
    for (int i = 0; i < 64; i++) {
        int v = p[i];
        if (v < 0 || v >= NN) return false;
        if (v != v0) varied = true;
    }
    return varied;
}
__device__ bool probe_edges64(const long long* p) {
    bool varied = false; long long v0 = p[0];
    for (int i = 0; i < 64; i++) {
        long long v = p[i];
        if (v < 0 || v >= NN) return false;
        if (v != v0) varied = true;
    }
    return varied;
}

__global__ void probe_kernel(Cands c) {
    if (threadIdx.x != 0 || blockIdx.x != 0) return;
    Sel s;
    s.x = c.xc[0];
    for (int i = 0; i < c.nx; i++)
        if (probe_variedf(c.xc[i], 64)) { s.x = c.xc[i]; break; }
    s.is64 = 0; s.ei32 = (const int*)c.ec[0]; s.ei64 = (const long long*)c.ec[0];
    for (int i = 0; i < c.ne; i++) {
        const int* p32 = (const int*)c.ec[i];
        if (probe_edges32(p32) && probe_edges32(p32 + EE)) { s.ei32 = p32; s.is64 = 0; break; }
        const long long* p64 = (const long long*)c.ec[i];
        if (probe_edges64(p64) && probe_edges64(p64 + EE)) { s.ei64 = p64; s.is64 = 1; break; }
    }
    s.W1_rel = nullptr; s.W1_root = nullptr;
    for (int i = 0; i < c.n1; i++)
        if (probe_variedf(c.w1c[i], 64)) {
            if (!s.W1_rel) s.W1_rel = c.w1c[i];
            else if (!s.W1_root) { s.W1_root = c.w1c[i]; break; }
        }
    if (!s.W1_rel)  s.W1_rel  = c.w1c[0];
    if (!s.W1_root) s.W1_root = c.w1c[c.n1 > 1 ? 1 : 0];
    s.W2_rel = nullptr; s.W2_root = nullptr;
    for (int i = 0; i < c.n2; i++)
        if (probe_variedf(c.w2c[i], 64)) {
            if (!s.W2_rel) s.W2_rel = c.w2c[i];
            else if (!s.W2_root) { s.W2_root = c.w2c[i]; break; }
        }
    if (!s.W2_rel)  s.W2_rel  = c.w2c[0];
    if (!s.W2_root) s.W2_root = c.w2c[c.n2 > 1 ? 1 : 0];
    s.b1 = c.b1c[0];
    for (int i = 0; i < c.nb1; i++)
        if (probe_variedf(c.b1c[i], 64)) { s.b1 = c.b1c[i]; break; }
    s.b2 = c.b2c[0];
    for (int i = 0; i < c.nb2; i++)
        if (probe_variedf(c.b2c[i], 64)) { s.b2 = c.b2c[i]; break; }
    g_sel = s;
}

// Zero CSR counters (MUST complete before hist_kernel's histogram).
__global__ __launch_bounds__(256) void zero_kernel() {
    int i = blockIdx.x * blockDim.x + threadIdx.x;
    if (i < NN) { g_cnt[i] = 0; g_cur[i] = 0; }
}

// Count histogram directly from the input edge buffer.
__global__ __launch_bounds__(256) void hist_kernel() {
    int i = blockIdx.x * blockDim.x + threadIdx.x;
    if (i >= EE) return;
    int d = g_sel.is64 ? (int)g_sel.ei64[i + EE] : g_sel.ei32[i + EE];
    atomicAdd(&g_cnt[d], 1);
}

// ---- 3-phase exclusive scan of g_cnt -> g_off -------------------------------
__global__ __launch_bounds__(1024) void scan1_kernel() {
    __shared__ int warpsum[32];
    int b = blockIdx.x, t = threadIdx.x;
    int idx = b * 1024 + t;
    int v = (idx < NN) ? g_cnt[idx] : 0;
    int x = v;
#pragma unroll
    for (int o = 1; o < 32; o <<= 1) {
        int y = __shfl_up_sync(0xFFFFFFFFu, x, o);
        if ((t & 31) >= o) x += y;
    }
    if ((t & 31) == 31) warpsum[t >> 5] = x;
    __syncthreads();
    if (t < 32) {
        int w = warpsum[t];
#pragma unroll
        for (int o = 1; o < 32; o <<= 1) {
            int y = __shfl_up_sync(0xFFFFFFFFu, w, o);
            if (t >= o) w += y;
        }
        warpsum[t] = w;
    }
    __syncthreads();
    int ex = x - v + ((t >= 32) ? warpsum[(t >> 5) - 1] : 0);
    if (idx < NN) g_off[idx] = ex;
    if (t == 1023) g_bsum[b] = ex + v;
}

__global__ void scan2_kernel() {
    if (threadIdx.x != 0) return;
    int acc = 0;
    for (int i = 0; i < SCAN_BLKS; i++) { g_boff[i] = acc; acc += g_bsum[i]; }
    g_off[NN] = acc;
}

__global__ __launch_bounds__(256) void scan3_kernel() {
    int i = blockIdx.x * blockDim.x + threadIdx.x;
    if (i < NN) g_off[i] += g_boff[i >> 10];
}

// CSR adjacency fill, reading src/dst straight from the input buffer.
__global__ __launch_bounds__(256) void fill_kernel() {
    int e = blockIdx.x * blockDim.x + threadIdx.x;
    if (e >= EE) return;
    int s, d;
    if (g_sel.is64) { s = (int)g_sel.ei64[e]; d = (int)g_sel.ei64[e + EE]; }
    else            { s = g_sel.ei32[e];      d = g_sel.ei32[e + EE]; }
    int pos = atomicAdd(&g_cur[d], 1);
    g_eidx[g_off[d] + pos] = s;
}

__global__ void prep_kernel() {
    int i = blockIdx.x * blockDim.x + threadIdx.x;
    const float* W1_rel  = g_sel.W1_rel;
    const float* W1_root = g_sel.W1_root;
    const float* W2_rel  = g_sel.W2_rel;
    const float* W2_root = g_sel.W2_root;
    if (i < 128 * 256) {
        int k = i >> 8, j = i & 255;
        g_Wt1[i] = (j < 128) ? W1_rel[j * 128 + k] : W1_root[(j - 128) * 128 + k];
    }
    if (i < 128 * 128) {
        int k = i >> 7, j = i & 127;
        g_Wt2[i] = (j < 64) ? W2_rel[j * 128 + k] : W2_root[(j - 64) * 128 + k];
    }
}

// ---------------- GEMM ------------------------------------------------------
template <int CO, int SPLIT, bool L1>
__global__ __launch_bounds__(256) void sgemm_dual(float* __restrict__ outB_ext, int n)
{
    const float* __restrict__ A    = L1 ? g_sel.x : g_h;   // g_h already relu'd
    const float* __restrict__ bias = L1 ? g_sel.b1 : g_sel.b2;
    const float* __restrict__ Wt   = L1 ? g_Wt1 : g_Wt2;
    float* __restrict__ outA = L1 ? g_t1 : g_t2;
    float* __restrict__ outB = L1 ? g_h : outB_ext;

    __shared__ float As[8][128];
    __shared__ float Ws[8][128];

    const int t = threadIdx.x;
    const int rowTile = blockIdx.x * 128;
    const int colTile = blockIdx.y * 128;

    const int a_r = t >> 1;
    const int a_c = (t & 1) * 4;
    const int w_r = t >> 5;
    const int w_c = (t & 31) * 4;
    const int tx = t & 15, ty = t >> 4;

    float acc[8][8];
#pragma unroll
    for (int i = 0; i < 8; i++)
#pragma unroll
        for (int j = 0; j < 8; j++) acc[i][j] = 0.f;

    const int gr_a = rowTile + a_r;
    for (int k0 = 0; k0 < 128; k0 += 8) {
        float4 av = make_float4(0.f, 0.f, 0.f, 0.f);
        if (gr_a < n) av = *(const float4*)(A + (size_t)gr_a * 128 + k0 + a_c);
        As[a_c + 0][a_r] = av.x;
        As[a_c + 1][a_r] = av.y;
        As[a_c + 2][a_r] = av.z;
        As[a_c + 3][a_r] = av.w;
        *(float4*)&Ws[w_r][w_c] = *(const float4*)(Wt + (size_t)(k0 + w_r) * CO + colTile + w_c);
        __syncthreads();
#pragma unroll
        for (int kk = 0; kk < 8; kk++) {
            float a[8], b[8];
            *(float4*)&a[0] = *(float4*)&As[kk][ty * 8];
            *(float4*)&a[4] = *(float4*)&As[kk][ty * 8 + 4];
            *(float4*)&b[0] = *(float4*)&Ws[kk][tx * 8];
            *(float4*)&b[4] = *(float4*)&Ws[kk][tx * 8 + 4];
#pragma unroll
            for (int i = 0; i < 8; i++)
#pragma unroll
                for (int j = 0; j < 8; j++) acc[i][j] = fmaf(a[i], b[j], acc[i][j]);
        }
        __syncthreads();
    }

#pragma unroll
    for (int i = 0; i < 8; i++) {
        int gr = rowTile + ty * 8 + i;
        if (gr >= n) continue;
#pragma unroll
        for (int j = 0; j < 8; j++) {
            int gc = colTile + tx * 8 + j;
            float v = acc[i][j];
            if (gc < SPLIT) outA[(size_t)gr * SPLIT + gc] = v;
            else            outB[(size_t)gr * (CO - SPLIT) + (gc - SPLIT)] = v + bias[gc - SPLIT];
        }
    }
}

// ---------------- gather aggregation (CSR) -----------------------------------
__global__ __launch_bounds__(256) void gather128_kernel() {
    int node = (blockIdx.x * blockDim.x + threadIdx.x) >> 5;
    int lane = threadIdx.x & 31;
    if (node >= NN) return;
    int beg = __ldg(g_off + node), end = __ldg(g_off + node + 1);
    float* row = g_h + (size_t)node * 128 + lane * 4;
    float4 acc = *(float4*)row;
    int e = beg;
    for (; e + 1 < end; e += 2) {
        int s0 = __ldg(g_eidx + e);
        int s1 = __ldg(g_eidx + e + 1);
        float4 v0 = *(const float4*)(g_t1 + (size_t)s0 * 128 + lane * 4);
        float4 v1 = *(const float4*)(g_t1 + (size_t)s1 * 128 + lane * 4);
        acc.x += v0.x + v1.x; acc.y += v0.y + v1.y;
        acc.z += v0.z + v1.z; acc.w += v0.w + v1.w;
    }
    if (e < end) {
        int s0 = __ldg(g_eidx + e);
        float4 v0 = *(const float4*)(g_t1 + (size_t)s0 * 128 + lane * 4);
        acc.x += v0.x; acc.y += v0.y; acc.z += v0.z; acc.w += v0.w;
    }
    acc.x = fmaxf(acc.x, 0.f); acc.y = fmaxf(acc.y, 0.f);
    acc.z = fmaxf(acc.z, 0.f); acc.w = fmaxf(acc.w, 0.f);
    *(float4*)row = acc;
}

__global__ __launch_bounds__(256) void gather64_kernel(float* __restrict__ out) {
    int node = (blockIdx.x * blockDim.x + threadIdx.x) >> 5;
    int lane = threadIdx.x & 31;
    if (node >= NN) return;
    int beg = __ldg(g_off + node), end = __ldg(g_off + node + 1);
    float* row = out + (size_t)node * 64 + lane * 2;
    float2 acc = *(float2*)row;
    int e = beg;
    for (; e + 1 < end; e += 2) {
        int s0 = __ldg(g_eidx + e);
        int s1 = __ldg(g_eidx + e + 1);
        float2 v0 = *(const float2*)(g_t2 + (size_t)s0 * 64 + lane * 2);
        float2 v1 = *(const float2*)(g_t2 + (size_t)s1 * 64 + lane * 2);
        acc.x += v0.x + v1.x; acc.y += v0.y + v1.y;
    }
    if (e < end) {
        int s0 = __ldg(g_eidx + e);
        float2 v0 = *(const float2*)(g_t2 + (size_t)s0 * 64 + lane * 2);
        acc.x += v0.x; acc.y += v0.y;
    }
    *(float2*)row = acc;
}

// ---------------- launch ----------------------------------------------------
extern "C" void kernel_launch(void* const* d_in, const int* in_sizes, int n_in,
                              void* d_out, int out_size) {
    Cands c;
    c.nx = c.ne = c.n1 = c.n2 = c.nb1 = c.nb2 = 0;
    for (int i = 0; i < MAXC; i++) {
        c.xc[i] = nullptr; c.ec[i] = nullptr; c.w1c[i] = nullptr;
        c.w2c[i] = nullptr; c.b1c[i] = nullptr; c.b2c[i] = nullptr;
    }
    for (int i = 0; i < n_in; i++) {
        switch (in_sizes[i]) {
            case 12800000: if (c.nx  < MAXC) c.xc [c.nx++ ] = (const float*)d_in[i]; break;
            case 6400000:  if (c.ne  < MAXC) c.ec [c.ne++ ] = d_in[i]; break;
            case 16384:    if (c.n1  < MAXC) c.w1c[c.n1++ ] = (const float*)d_in[i]; break;
            case 8192:     if (c.n2  < MAXC) c.w2c[c.n2++ ] = (const float*)d_in[i]; break;
            case 128:      if (c.nb1 < MAXC) c.b1c[c.nb1++] = (const float*)d_in[i]; break;
            case 64:       if (c.nb2 < MAXC) c.b2c[c.nb2++] = (const float*)d_in[i]; break;
            default: break;
        }
    }
    float* out = (float*)d_out;

    // Fork a side stream for the CSR build so it overlaps with prep+GEMM1.
    cudaStream_t sB;
    cudaStreamCreateWithFlags(&sB, cudaStreamNonBlocking);
    cudaEvent_t evFork, evJoin;
    cudaEventCreateWithFlags(&evFork, cudaEventDisableTiming);
    cudaEventCreateWithFlags(&evJoin, cudaEventDisableTiming);

    probe_kernel<<<1, 32>>>(c);
    cudaEventRecord(evFork, 0);
    cudaStreamWaitEvent(sB, evFork, 0);

    // Branch B (stream sB): CSR build
    zero_kernel<<<(NN + 255) / 256, 256, 0, sB>>>();
    hist_kernel<<<(EE + 255) / 256, 256, 0, sB>>>();
    scan1_kernel<<<SCAN_BLKS, 1024, 0, sB>>>();
    scan2_kernel<<<1, 32, 0, sB>>>();
    scan3_kernel<<<(NN + 255) / 256, 256, 0, sB>>>();
    fill_kernel<<<(EE + 255) / 256, 256, 0, sB>>>();
    cudaEventRecord(evJoin, sB);

    // Branch A (default stream): weights + layer-1 GEMM
    prep_kernel<<<128, 256>>>();
    const int rowBlocks = (NN + 127) / 128;
    sgemm_dual<256, 128, true><<<dim3(rowBlocks, 2), 256>>>(nullptr, NN);

    // Join: gather needs both GEMM1 (t1, g_h) and the CSR.
    cudaStreamWaitEvent(0, evJoin, 0);
    gather128_kernel<<<(NN * 32 + 255) / 256, 256>>>();

    // Layer 2: t2 = h@W2_rel^T ; d_out = h@W2_root^T + b2
    sgemm_dual<128, 64, false><<<dim3(rowBlocks, 1), 256>>>(out, NN);

    // d_out += gather(t2)
    gather64_kernel<<<(NN * 32 + 255) / 256, 256>>>(out);
}

// round 16
// speedup vs baseline: 3.8200x; 1.3184x over previous
#include <cuda_runtime.h>
#include <cstdint>
#include <math.h>

#define NN 100000
#define EE 3200000
#define MAXC 4
#define SCAN_BLKS ((NN + 1023) / 1024)   // 98

// ---------------- scratch (device globals — no allocation allowed) ----------
__device__ float g_t1[(size_t)NN * 128];   // x @ W1_rel^T
__device__ float g_h [(size_t)NN * 128];   // x@W1_root^T + b1, += agg, relu
__device__ float g_t2[(size_t)NN * 64];    // relu(h) @ W2_rel^T
// CSR (dst-sorted)
__device__ int   g_cnt[NN];
__device__ int   g_cur[NN];
__device__ int   g_off[NN + 1];
__device__ int   g_eidx[EE];
__device__ int   g_bsum[SCAN_BLKS];
__device__ int   g_boff[SCAN_BLKS];

// ---------------- input disambiguation --------------------------------------
struct Cands {
    const float* xc[MAXC];  int nx;
    const void*  ec[MAXC];  int ne;
    const float* w1c[MAXC]; int n1;
    const float* w2c[MAXC]; int n2;
    const float* b1c[MAXC]; int nb1;
    const float* b2c[MAXC]; int nb2;
};
struct Sel {
    const float* x;
    const long long* ei64;
    const int* ei32;
    int is64;
    const float* W1_rel; const float* W1_root;
    const float* W2_rel; const float* W2_root;
    const float* b1; const float* b2;
};
__device__ Sel g_sel;

__device__ bool probe_variedf(const float* p, int n) {
    if (!p) return false;
    bool varied = false; int big = 0;
    float v0 = p[0];
    for (int i = 0; i < n; i++) {
        float v = p[i];
        if (!isfinite(v) || fabsf(v) > 1e6f) return false;
        if (v != v0) varied = true;
        if (fabsf(v) > 1e-3f) big++;
    }
    return varied && big >= n / 4;
}
__device__ bool probe_edges32(const int* p) {
    bool varied = false; int v0 = p[0];
    for (int i = 0; i < 64; i++) {
        int v = p[i];
        if (v < 0 || v >= NN) return false;
        if (v != v0) varied = true;
    }
    return varied;
}
__device__ bool probe_edges64(const long long* p) {
    bool varied = false; long long v0 = p[0];
    for (int i = 0; i < 64; i++) {
        long long v = p[i];
        if (v < 0 || v >= NN) return false;
        if (v != v0) varied = true;
    }
    return varied;
}

__global__ void probe_kernel(Cands c) {
    if (threadIdx.x != 0 || blockIdx.x != 0) return;
    Sel s;
    s.x = c.xc[0];
    for (int i = 0; i < c.nx; i++)
        if (probe_variedf(c.xc[i], 64)) { s.x = c.xc[i]; break; }
    s.is64 = 0; s.ei32 = (const int*)c.ec[0]; s.ei64 = (const long long*)c.ec[0];
    for (int i = 0; i < c.ne; i++) {
        const int* p32 = (const int*)c.ec[i];
        if (probe_edges32(p32) && probe_edges32(p32 + EE)) { s.ei32 = p32; s.is64 = 0; break; }
        const long long* p64 = (const long long*)c.ec[i];
        if (probe_edges64(p64) && probe_edges64(p64 + EE)) { s.ei64 = p64; s.is64 = 1; break; }
    }
    s.W1_rel = nullptr; s.W1_root = nullptr;
    for (int i = 0; i < c.n1; i++)
        if (probe_variedf(c.w1c[i], 64)) {
            if (!s.W1_rel) s.W1_rel = c.w1c[i];
            else if (!s.W1_root) { s.W1_root = c.w1c[i]; break; }
        }
    if (!s.W1_rel)  s.W1_rel  = c.w1c[0];
    if (!s.W1_root) s.W1_root = c.w1c[c.n1 > 1 ? 1 : 0];
    s.W2_rel = nullptr; s.W2_root = nullptr;
    for (int i = 0; i < c.n2; i++)
        if (probe_variedf(c.w2c[i], 64)) {
            if (!s.W2_rel) s.W2_rel = c.w2c[i];
            else if (!s.W2_root) { s.W2_root = c.w2c[i]; break; }
        }
    if (!s.W2_rel)  s.W2_rel  = c.w2c[0];
    if (!s.W2_root) s.W2_root = c.w2c[c.n2 > 1 ? 1 : 0];
    s.b1 = c.b1c[0];
    for (int i = 0; i < c.nb1; i++)
        if (probe_variedf(c.b1c[i], 64)) { s.b1 = c.b1c[i]; break; }
    s.b2 = c.b2c[0];
    for (int i = 0; i < c.nb2; i++)
        if (probe_variedf(c.b2c[i], 64)) { s.b2 = c.b2c[i]; break; }
    g_sel = s;
}

// ---------------- CSR build --------------------------------------------------
__global__ __launch_bounds__(256) void zero_kernel() {
    int i = blockIdx.x * blockDim.x + threadIdx.x;
    if (i < NN) { g_cnt[i] = 0; g_cur[i] = 0; }
}

__global__ __launch_bounds__(256) void hist_kernel() {
    int i = blockIdx.x * blockDim.x + threadIdx.x;
    if (i >= EE) return;
    int d = g_sel.is64 ? (int)g_sel.ei64[i + EE] : g_sel.ei32[i + EE];
    atomicAdd(&g_cnt[d], 1);
}

__global__ __launch_bounds__(1024) void scan1_kernel() {
    __shared__ int warpsum[32];
    int b = blockIdx.x, t = threadIdx.x;
    int idx = b * 1024 + t;
    int v = (idx < NN) ? g_cnt[idx] : 0;
    int x = v;
#pragma unroll
    for (int o = 1; o < 32; o <<= 1) {
        int y = __shfl_up_sync(0xFFFFFFFFu, x, o);
        if ((t & 31) >= o) x += y;
    }
    if ((t & 31) == 31) warpsum[t >> 5] = x;
    __syncthreads();
    if (t < 32) {
        int w = warpsum[t];
#pragma unroll
        for (int o = 1; o < 32; o <<= 1) {
            int y = __shfl_up_sync(0xFFFFFFFFu, w, o);
            if (t >= o) w += y;
        }
        warpsum[t] = w;
    }
    __syncthreads();
    int ex = x - v + ((t >= 32) ? warpsum[(t >> 5) - 1] : 0);
    if (idx < NN) g_off[idx] = ex;
    if (t == 1023) g_bsum[b] = ex + v;
}

__global__ void scan2_kernel() {
    if (threadIdx.x != 0) return;
    int acc = 0;
    for (int i = 0; i < SCAN_BLKS; i++) { g_boff[i] = acc; acc += g_bsum[i]; }
    g_off[NN] = acc;
}

__global__ __launch_bounds__(256) void scan3_kernel() {
    int i = blockIdx.x * blockDim.x + threadIdx.x;
    if (i < NN) g_off[i] += g_boff[i >> 10];
}

__global__ __launch_bounds__(256) void fill_kernel() {
    int e = blockIdx.x * blockDim.x + threadIdx.x;
    if (e >= EE) return;
    int s, d;
    if (g_sel.is64) { s = (int)g_sel.ei64[e]; d = (int)g_sel.ei64[e + EE]; }
    else            { s = g_sel.ei32[e];      d = g_sel.ei32[e + EE]; }
    int pos = atomicAdd(&g_cur[d], 1);
    g_eidx[g_off[d] + pos] = s;
}

// ---------------- tf32 tensor-core GEMM -------------------------------------
// C[n, 128cols-per-blockcol] = A[n,128] @ W^T with 3xTF32 accuracy recovery.
// B fragments come straight from W[out][in] row-major (n-major) layout.
__device__ __forceinline__ uint32_t swz(uint32_t o) { return o ^ ((o >> 3) & 0x70); }

__device__ __forceinline__ void split_tf32(uint32_t raw, uint32_t& hi, uint32_t& lo) {
    float f = __uint_as_float(raw);
    asm("cvt.rna.tf32.f32 %0, %1;" : "=r"(hi) : "f"(f));
    float fl = f - __uint_as_float(hi);
    asm("cvt.rna.tf32.f32 %0, %1;" : "=r"(lo) : "f"(fl));
}

#define LDSM4(r0, r1, r2, r3, addr) \
    asm volatile("ldmatrix.sync.aligned.m8n8.x4.shared.b16 {%0,%1,%2,%3},[%4];" \
                 : "=r"(r0), "=r"(r1), "=r"(r2), "=r"(r3) : "r"(addr))

#define MMA8(c, a, b) \
    asm volatile("mma.sync.aligned.m16n8k8.row.col.f32.tf32.tf32.f32 " \
                 "{%0,%1,%2,%3},{%4,%5,%6,%7},{%8,%9},{%0,%1,%2,%3};" \
                 : "+f"((c)[0]), "+f"((c)[1]), "+f"((c)[2]), "+f"((c)[3]) \
                 : "r"((a)[0]), "r"((a)[1]), "r"((a)[2]), "r"((a)[3]), \
                   "r"((b)[0]), "r"((b)[1]))

template <bool IS_L1>
__global__ __launch_bounds__(256, 2) void mma_dual(float* __restrict__ outB_ext)
{
    __shared__ float As[128 * 32];
    __shared__ float Bs[128 * 32];

    const int t = threadIdx.x;
    const int by = blockIdx.y;
    const int rowTile = blockIdx.x * 128;

    const float* __restrict__ A = IS_L1 ? g_sel.x : g_h;
    const float* __restrict__ Bw0 = IS_L1 ? (by ? g_sel.W1_root : g_sel.W1_rel) : g_sel.W2_rel;
    const float* __restrict__ Bw1 = IS_L1 ? Bw0 : g_sel.W2_root;
    float* __restrict__ out2 = outB_ext;

    uint32_t asA = (uint32_t)__cvta_generic_to_shared(As);
    uint32_t asB = (uint32_t)__cvta_generic_to_shared(Bs);

    const int wid = t >> 5, lane = t & 31;
    const int wm = wid & 3, wn = wid >> 2;          // 4x2 warp grid

    float C[2][8][4];
#pragma unroll
    for (int i = 0; i < 2; i++)
#pragma unroll
        for (int j = 0; j < 8; j++)
#pragma unroll
            for (int k = 0; k < 4; k++) C[i][j][k] = 0.f;

    // cp.async staging assignment: row r = t>>1, 16B-units (t&1)*4 .. +3
    const int r = t >> 1;
    const int useg = (t & 1) * 4;
    const float* aRow = A + (size_t)(rowTile + r) * 128;
    const float* bRow = IS_L1 ? (Bw0 + r * 128)
                              : (r < 64 ? Bw0 + r * 128 : Bw1 + (r - 64) * 128);
    const int aval = (rowTile + r) < NN ? 16 : 0;

    for (int kc = 0; kc < 4; kc++) {
#pragma unroll
        for (int i = 0; i < 4; i++) {
            uint32_t du = swz((uint32_t)(r * 128 + (useg + i) * 16));
            asm volatile("cp.async.ca.shared.global [%0],[%1],16,%2;"
                         :: "r"(asA + du), "l"(aRow + kc * 32 + (useg + i) * 4), "r"(aval));
            asm volatile("cp.async.ca.shared.global [%0],[%1],16;"
                         :: "r"(asB + du), "l"(bRow + kc * 32 + (useg + i) * 4));
        }
        asm volatile("cp.async.commit_group;");
        asm volatile("cp.async.wait_group 0;");
        __syncthreads();

#pragma unroll
        for (int ks = 0; ks < 4; ks++) {
            uint32_t ahi[2][4], alo[2][4];
#pragma unroll
            for (int mt = 0; mt < 2; mt++) {
                uint32_t a0, a1, a2, a3;
                uint32_t addr = asA + swz((uint32_t)((wm * 32 + mt * 16 + (lane & 15)) * 128
                                                     + (2 * ks + (lane >> 4)) * 16));
                LDSM4(a0, a1, a2, a3, addr);
                split_tf32(a0, ahi[mt][0], alo[mt][0]);
                split_tf32(a1, ahi[mt][1], alo[mt][1]);
                split_tf32(a2, ahi[mt][2], alo[mt][2]);
                split_tf32(a3, ahi[mt][3], alo[mt][3]);
            }
#pragma unroll
            for (int pr = 0; pr < 4; pr++) {
                uint32_t b0, b1r, b2r, b3;
                uint32_t addr = asB + swz((uint32_t)((wn * 64 + pr * 16 + (lane & 7) + ((lane >> 1) & 8)) * 128
                                                     + (2 * ks + ((lane >> 3) & 1)) * 16));
                LDSM4(b0, b1r, b2r, b3, addr);
                uint32_t bh[4], bl[4];
                split_tf32(b0, bh[0], bl[0]);
                split_tf32(b1r, bh[1], bl[1]);
                split_tf32(b2r, bh[2], bl[2]);
                split_tf32(b3, bh[3], bl[3]);
#pragma unroll
                for (int mt = 0; mt < 2; mt++) {
                    MMA8(C[mt][pr * 2 + 0], ahi[mt], bh + 0);
                    MMA8(C[mt][pr * 2 + 0], alo[mt], bh + 0);
                    MMA8(C[mt][pr * 2 + 0], ahi[mt], bl + 0);
                    MMA8(C[mt][pr * 2 + 1], ahi[mt], bh + 2);
                    MMA8(C[mt][pr * 2 + 1], alo[mt], bh + 2);
                    MMA8(C[mt][pr * 2 + 1], ahi[mt], bl + 2);
                }
            }
        }
        __syncthreads();
    }

    // Epilogue
    const float* __restrict__ bias1 = g_sel.b1;
    const float* __restrict__ bias2 = g_sel.b2;
#pragma unroll
    for (int mt = 0; mt < 2; mt++) {
        int gr0 = rowTile + wm * 32 + mt * 16 + (lane >> 2);
#pragma unroll
        for (int nt = 0; nt < 8; nt++) {
            int lc = wn * 64 + nt * 8 + (lane & 3) * 2;
#pragma unroll
            for (int h = 0; h < 2; h++) {
                int gr = gr0 + h * 8;
                if (gr >= NN) continue;
                float v0 = C[mt][nt][h * 2 + 0];
                float v1 = C[mt][nt][h * 2 + 1];
                if (IS_L1) {
                    if (by == 0) {
                        *(float2*)&g_t1[(size_t)gr * 128 + lc] = make_float2(v0, v1);
                    } else {
                        *(float2*)&g_h[(size_t)gr * 128 + lc] =
                            make_float2(v0 + bias1[lc], v1 + bias1[lc + 1]);
                    }
                } else {
                    if (lc < 64) {
                        *(float2*)&g_t2[(size_t)gr * 64 + lc] = make_float2(v0, v1);
                    } else {
                        *(float2*)&out2[(size_t)gr * 64 + lc - 64] =
                            make_float2(v0 + bias2[lc - 64], v1 + bias2[lc - 63]);
                    }
                }
            }
        }
    }
}

// ---------------- gather aggregation (CSR) -----------------------------------
__global__ __launch_bounds__(256) void gather128_kernel() {
    int node = (blockIdx.x * blockDim.x + threadIdx.x) >> 5;
    int lane = threadIdx.x & 31;
    if (node >= NN) return;
    int beg = __ldg(g_off + node), end = __ldg(g_off + node + 1);
    float* row = g_h + (size_t)node * 128 + lane * 4;
    float4 acc = *(float4*)row;
    int e = beg;
    for (; e + 1 < end; e += 2) {
        int s0 = __ldg(g_eidx + e);
        int s1 = __ldg(g_eidx + e + 1);
        float4 v0 = *(const float4*)(g_t1 + (size_t)s0 * 128 + lane * 4);
        float4 v1 = *(const float4*)(g_t1 + (size_t)s1 * 128 + lane * 4);
        acc.x += v0.x + v1.x; acc.y += v0.y + v1.y;
        acc.z += v0.z + v1.z; acc.w += v0.w + v1.w;
    }
    if (e < end) {
        int s0 = __ldg(g_eidx + e);
        float4 v0 = *(const float4*)(g_t1 + (size_t)s0 * 128 + lane * 4);
        acc.x += v0.x; acc.y += v0.y; acc.z += v0.z; acc.w += v0.w;
    }
    acc.x = fmaxf(acc.x, 0.f); acc.y = fmaxf(acc.y, 0.f);
    acc.z = fmaxf(acc.z, 0.f); acc.w = fmaxf(acc.w, 0.f);
    *(float4*)row = acc;
}

__global__ __launch_bounds__(256) void gather64_kernel(float* __restrict__ out) {
    int node = (blockIdx.x * blockDim.x + threadIdx.x) >> 5;
    int lane = threadIdx.x & 31;
    if (node >= NN) return;
    int beg = __ldg(g_off + node), end = __ldg(g_off + node + 1);
    float* row = out + (size_t)node * 64 + lane * 2;
    float2 acc = *(float2*)row;
    int e = beg;
    for (; e + 1 < end; e += 2) {
        int s0 = __ldg(g_eidx + e);
        int s1 = __ldg(g_eidx + e + 1);
        float2 v0 = *(const float2*)(g_t2 + (size_t)s0 * 64 + lane * 2);
        float2 v1 = *(const float2*)(g_t2 + (size_t)s1 * 64 + lane * 2);
        acc.x += v0.x + v1.x; acc.y += v0.y + v1.y;
    }
    if (e < end) {
        int s0 = __ldg(g_eidx + e);
        float2 v0 = *(const float2*)(g_t2 + (size_t)s0 * 64 + lane * 2);
        acc.x += v0.x; acc.y += v0.y;
    }
    *(float2*)row = acc;
}

// ---------------- launch ----------------------------------------------------
extern "C" void kernel_launch(void* const* d_in, const int* in_sizes, int n_in,
                              void* d_out, int out_size) {
    Cands c;
    c.nx = c.ne = c.n1 = c.n2 = c.nb1 = c.nb2 = 0;
    for (int i = 0; i < MAXC; i++) {
        c.xc[i] = nullptr; c.ec[i] = nullptr; c.w1c[i] = nullptr;
        c.w2c[i] = nullptr; c.b1c[i] = nullptr; c.b2c[i] = nullptr;
    }
    for (int i = 0; i < n_in; i++) {
        switch (in_sizes[i]) {
            case 12800000: if (c.nx  < MAXC) c.xc [c.nx++ ] = (const float*)d_in[i]; break;
            case 6400000:  if (c.ne  < MAXC) c.ec [c.ne++ ] = d_in[i]; break;
            case 16384:    if (c.n1  < MAXC) c.w1c[c.n1++ ] = (const float*)d_in[i]; break;
            case 8192:     if (c.n2  < MAXC) c.w2c[c.n2++ ] = (const float*)d_in[i]; break;
            case 128:      if (c.nb1 < MAXC) c.b1c[c.nb1++] = (const float*)d_in[i]; break;
            case 64:       if (c.nb2 < MAXC) c.b2c[c.nb2++] = (const float*)d_in[i]; break;
            default: break;
        }
    }
    float* out = (float*)d_out;

    cudaStream_t sB;
    cudaStreamCreateWithFlags(&sB, cudaStreamNonBlocking);
    cudaEvent_t evFork, evJoin;
    cudaEventCreateWithFlags(&evFork, cudaEventDisableTiming);
    cudaEventCreateWithFlags(&evJoin, cudaEventDisableTiming);

    probe_kernel<<<1, 32>>>(c);
    cudaEventRecord(evFork, 0);
    cudaStreamWaitEvent(sB, evFork, 0);

    // Branch B: CSR build
    zero_kernel<<<(NN + 255) / 256, 256, 0, sB>>>();
    hist_kernel<<<(EE + 255) / 256, 256, 0, sB>>>();
    scan1_kernel<<<SCAN_BLKS, 1024, 0, sB>>>();
    scan2_kernel<<<1, 32, 0, sB>>>();
    scan3_kernel<<<(NN + 255) / 256, 256, 0, sB>>>();
    fill_kernel<<<(EE + 255) / 256, 256, 0, sB>>>();
    cudaEventRecord(evJoin, sB);

    // Branch A: layer-1 GEMM (tf32 tensor cores, 3xTF32)
    const int rowBlocks = (NN + 127) / 128;  // 782
    mma_dual<true><<<dim3(rowBlocks, 2), 256>>>(nullptr);

    cudaStreamWaitEvent(0, evJoin, 0);
    gather128_kernel<<<(NN * 32 + 255) / 256, 256>>>();

    mma_dual<false><<<dim3(rowBlocks, 1), 256>>>(out);

    gather64_kernel<<<(NN * 32 + 255) / 256, 256>>>(out);
}

// round 17
// speedup vs baseline: 3.9472x; 1.0333x over previous
#include <cuda_runtime.h>
#include <cstdint>
#include <math.h>

#define NN 100000
#define EE 3200000
#define MAXC 4
#define SCAN_BLKS ((NN + 1023) / 1024)   // 98

// ---------------- scratch (device globals — no allocation allowed) ----------
__device__ float g_t1[(size_t)NN * 128];   // x @ W1_rel^T
__device__ float g_h [(size_t)NN * 128];   // x@W1_root^T + b1, += agg, relu
__device__ float g_t2[(size_t)NN * 64];    // relu(h) @ W2_rel^T
// CSR (dst-sorted)
__device__ int   g_cnt[NN];
__device__ int   g_cur[NN];
__device__ int   g_off[NN + 1];
__device__ int   g_eidx[EE];
__device__ int   g_bsum[SCAN_BLKS];
__device__ int   g_boff[SCAN_BLKS];

// ---------------- input disambiguation --------------------------------------
struct Cands {
    const float* xc[MAXC];  int nx;
    const void*  ec[MAXC];  int ne;
    const float* w1c[MAXC]; int n1;
    const float* w2c[MAXC]; int n2;
    const float* b1c[MAXC]; int nb1;
    const float* b2c[MAXC]; int nb2;
};
struct Sel {
    const float* x;
    const long long* ei64;
    const int* ei32;
    int is64;
    const float* W1_rel; const float* W1_root;
    const float* W2_rel; const float* W2_root;
    const float* b1; const float* b2;
};
__device__ Sel g_sel;

__device__ bool probe_variedf(const float* p, int n) {
    if (!p) return false;
    bool varied = false; int big = 0;
    float v0 = p[0];
    for (int i = 0; i < n; i++) {
        float v = p[i];
        if (!isfinite(v) || fabsf(v) > 1e6f) return false;
        if (v != v0) varied = true;
        if (fabsf(v) > 1e-3f) big++;
    }
    return varied && big >= n / 4;
}
__device__ bool probe_edges32(const int* p) {
    bool varied = false; int v0 = p[0];
    for (int i = 0; i < 64; i++) {
        int v = p[i];
        if (v < 0 || v >= NN) return false;
        if (v != v0) varied = true;
    }
    return varied;
}
__device__ bool probe_edges64(const long long* p) {
    bool varied = false; long long v0 = p[0];
    for (int i = 0; i < 64; i++) {
        long long v = p[i];
        if (v < 0 || v >= NN) return false;
        if (v != v0) varied = true;
    }
    return varied;
}

__global__ void probe_kernel(Cands c) {
    if (threadIdx.x != 0 || blockIdx.x != 0) return;
    Sel s;
    s.x = c.xc[0];
    for (int i = 0; i < c.nx; i++)
        if (probe_variedf(c.xc[i], 64)) { s.x = c.xc[i]; break; }
    s.is64 = 0; s.ei32 = (const int*)c.ec[0]; s.ei64 = (const long long*)c.ec[0];
    for (int i = 0; i < c.ne; i++) {
        const int* p32 = (const int*)c.ec[i];
        if (probe_edges32(p32) && probe_edges32(p32 + EE)) { s.ei32 = p32; s.is64 = 0; break; }
        const long long* p64 = (const long long*)c.ec[i];
        if (probe_edges64(p64) && probe_edges64(p64 + EE)) { s.ei64 = p64; s.is64 = 1; break; }
    }
    s.W1_rel = nullptr; s.W1_root = nullptr;
    for (int i = 0; i < c.n1; i++)
        if (probe_variedf(c.w1c[i], 64)) {
            if (!s.W1_rel) s.W1_rel = c.w1c[i];
            else if (!s.W1_root) { s.W1_root = c.w1c[i]; break; }
        }
    if (!s.W1_rel)  s.W1_rel  = c.w1c[0];
    if (!s.W1_root) s.W1_root = c.w1c[c.n1 > 1 ? 1 : 0];
    s.W2_rel = nullptr; s.W2_root = nullptr;
    for (int i = 0; i < c.n2; i++)
        if (probe_variedf(c.w2c[i], 64)) {
            if (!s.W2_rel) s.W2_rel = c.w2c[i];
            else if (!s.W2_root) { s.W2_root = c.w2c[i]; break; }
        }
    if (!s.W2_rel)  s.W2_rel  = c.w2c[0];
    if (!s.W2_root) s.W2_root = c.w2c[c.n2 > 1 ? 1 : 0];
    s.b1 = c.b1c[0];
    for (int i = 0; i < c.nb1; i++)
        if (probe_variedf(c.b1c[i], 64)) { s.b1 = c.b1c[i]; break; }
    s.b2 = c.b2c[0];
    for (int i = 0; i < c.nb2; i++)
        if (probe_variedf(c.b2c[i], 64)) { s.b2 = c.b2c[i]; break; }
    g_sel = s;
}

// ---------------- CSR build --------------------------------------------------
__global__ __launch_bounds__(256) void zero_kernel() {
    int i = blockIdx.x * blockDim.x + threadIdx.x;
    if (i < NN) { g_cnt[i] = 0; g_cur[i] = 0; }
}

__global__ __launch_bounds__(256) void hist_kernel() {
    int i = blockIdx.x * blockDim.x + threadIdx.x;
    if (i >= EE) return;
    int d = g_sel.is64 ? (int)g_sel.ei64[i + EE] : g_sel.ei32[i + EE];
    atomicAdd(&g_cnt[d], 1);
}

__global__ __launch_bounds__(1024) void scan1_kernel() {
    __shared__ int warpsum[32];
    int b = blockIdx.x, t = threadIdx.x;
    int idx = b * 1024 + t;
    int v = (idx < NN) ? g_cnt[idx] : 0;
    int x = v;
#pragma unroll
    for (int o = 1; o < 32; o <<= 1) {
        int y = __shfl_up_sync(0xFFFFFFFFu, x, o);
        if ((t & 31) >= o) x += y;
    }
    if ((t & 31) == 31) warpsum[t >> 5] = x;
    __syncthreads();
    if (t < 32) {
        int w = warpsum[t];
#pragma unroll
        for (int o = 1; o < 32; o <<= 1) {
            int y = __shfl_up_sync(0xFFFFFFFFu, w, o);
            if (t >= o) w += y;
        }
        warpsum[t] = w;
    }
    __syncthreads();
    int ex = x - v + ((t >= 32) ? warpsum[(t >> 5) - 1] : 0);
    if (idx < NN) g_off[idx] = ex;
    if (t == 1023) g_bsum[b] = ex + v;
}

__global__ void scan2_kernel() {
    if (threadIdx.x != 0) return;
    int acc = 0;
    for (int i = 0; i < SCAN_BLKS; i++) { g_boff[i] = acc; acc += g_bsum[i]; }
    g_off[NN] = acc;
}

__global__ __launch_bounds__(256) void scan3_kernel() {
    int i = blockIdx.x * blockDim.x + threadIdx.x;
    if (i < NN) g_off[i] += g_boff[i >> 10];
}

__global__ __launch_bounds__(256) void fill_kernel() {
    int e = blockIdx.x * blockDim.x + threadIdx.x;
    if (e >= EE) return;
    int s, d;
    if (g_sel.is64) { s = (int)g_sel.ei64[e]; d = (int)g_sel.ei64[e + EE]; }
    else            { s = g_sel.ei32[e];      d = g_sel.ei32[e + EE]; }
    int pos = atomicAdd(&g_cur[d], 1);
    g_eidx[g_off[d] + pos] = s;
}

// ---------------- tf32 tensor-core GEMM (2-stage pipelined) ------------------
__device__ __forceinline__ uint32_t swz(uint32_t o) { return o ^ ((o >> 3) & 0x70); }

__device__ __forceinline__ void split_tf32(uint32_t raw, uint32_t& hi, uint32_t& lo) {
    float f = __uint_as_float(raw);
    asm("cvt.rna.tf32.f32 %0, %1;" : "=r"(hi) : "f"(f));
    float fl = f - __uint_as_float(hi);
    asm("cvt.rna.tf32.f32 %0, %1;" : "=r"(lo) : "f"(fl));
}

#define LDSM4(r0, r1, r2, r3, addr) \
    asm volatile("ldmatrix.sync.aligned.m8n8.x4.shared.b16 {%0,%1,%2,%3},[%4];" \
                 : "=r"(r0), "=r"(r1), "=r"(r2), "=r"(r3) : "r"(addr))

#define MMA8(c, a, b) \
    asm volatile("mma.sync.aligned.m16n8k8.row.col.f32.tf32.tf32.f32 " \
                 "{%0,%1,%2,%3},{%4,%5,%6,%7},{%8,%9},{%0,%1,%2,%3};" \
                 : "+f"((c)[0]), "+f"((c)[1]), "+f"((c)[2]), "+f"((c)[3]) \
                 : "r"((a)[0]), "r"((a)[1]), "r"((a)[2]), "r"((a)[3]), \
                   "r"((b)[0]), "r"((b)[1]))

// Dynamic smem layout (bytes): A stage0 [0,16K), A stage1 [16K,32K),
//                              B stage0 [32K,48K), B stage1 [48K,64K)
#define STG_BYTES 16384
#define SMEM_TOTAL_MMA 65536

template <bool IS_L1>
__global__ __launch_bounds__(256, 2) void mma_dual(float* __restrict__ outB_ext)
{
    extern __shared__ float smem[];

    const int t = threadIdx.x;
    const int by = blockIdx.y;
    const int rowTile = blockIdx.x * 128;

    const float* __restrict__ A = IS_L1 ? g_sel.x : g_h;
    const float* __restrict__ Bw0 = IS_L1 ? (by ? g_sel.W1_root : g_sel.W1_rel) : g_sel.W2_rel;
    const float* __restrict__ Bw1 = IS_L1 ? Bw0 : g_sel.W2_root;
    float* __restrict__ out2 = outB_ext;

    uint32_t base = (uint32_t)__cvta_generic_to_shared(smem);

    const int wid = t >> 5, lane = t & 31;
    const int wm = wid & 3, wn = wid >> 2;          // 4x2 warp grid

    float C[2][8][4];
#pragma unroll
    for (int i = 0; i < 2; i++)
#pragma unroll
        for (int j = 0; j < 8; j++)
#pragma unroll
            for (int k = 0; k < 4; k++) C[i][j][k] = 0.f;

    // cp.async staging: row r = t>>1, 16B-units (t&1)*4 .. +3
    const int r = t >> 1;
    const int useg = (t & 1) * 4;
    const float* aRow = A + (size_t)(rowTile + r) * 128;
    const float* bRow = IS_L1 ? (Bw0 + r * 128)
                              : (r < 64 ? Bw0 + r * 128 : Bw1 + (r - 64) * 128);
    const int aval = (rowTile + r) < NN ? 16 : 0;

    // Issue chunk kc into stage st.
    auto issue = [&](int kc, int st) {
        uint32_t asA = base + st * STG_BYTES;
        uint32_t asB = base + 2 * STG_BYTES + st * STG_BYTES;
#pragma unroll
        for (int i = 0; i < 4; i++) {
            uint32_t du = swz((uint32_t)(r * 128 + (useg + i) * 16));
            asm volatile("cp.async.ca.shared.global [%0],[%1],16,%2;"
                         :: "r"(asA + du), "l"(aRow + kc * 32 + (useg + i) * 4), "r"(aval));
            asm volatile("cp.async.ca.shared.global [%0],[%1],16;"
                         :: "r"(asB + du), "l"(bRow + kc * 32 + (useg + i) * 4));
        }
        asm volatile("cp.async.commit_group;");
    };

    issue(0, 0);

    for (int kc = 0; kc < 4; kc++) {
        const int st = kc & 1;
        if (kc < 3) issue(kc + 1, st ^ 1);
        if (kc < 3) asm volatile("cp.async.wait_group 1;");
        else        asm volatile("cp.async.wait_group 0;");
        __syncthreads();

        uint32_t asA = base + st * STG_BYTES;
        uint32_t asB = base + 2 * STG_BYTES + st * STG_BYTES;

#pragma unroll
        for (int ks = 0; ks < 4; ks++) {
            uint32_t ahi[2][4], alo[2][4];
#pragma unroll
            for (int mt = 0; mt < 2; mt++) {
                uint32_t a0, a1, a2, a3;
                uint32_t addr = asA + swz((uint32_t)((wm * 32 + mt * 16 + (lane & 15)) * 128
                                                     + (2 * ks + (lane >> 4)) * 16));
                LDSM4(a0, a1, a2, a3, addr);
                split_tf32(a0, ahi[mt][0], alo[mt][0]);
                split_tf32(a1, ahi[mt][1], alo[mt][1]);
                split_tf32(a2, ahi[mt][2], alo[mt][2]);
                split_tf32(a3, ahi[mt][3], alo[mt][3]);
            }
#pragma unroll
            for (int pr = 0; pr < 4; pr++) {
                uint32_t b0, b1r, b2r, b3;
                uint32_t addr = asB + swz((uint32_t)((wn * 64 + pr * 16 + (lane & 7) + ((lane >> 1) & 8)) * 128
                                                     + (2 * ks + ((lane >> 3) & 1)) * 16));
                LDSM4(b0, b1r, b2r, b3, addr);
                uint32_t bh[4], bl[4];
                split_tf32(b0, bh[0], bl[0]);
                split_tf32(b1r, bh[1], bl[1]);
                split_tf32(b2r, bh[2], bl[2]);
                split_tf32(b3, bh[3], bl[3]);
#pragma unroll
                for (int mt = 0; mt < 2; mt++) {
                    MMA8(C[mt][pr * 2 + 0], ahi[mt], bh + 0);
                    MMA8(C[mt][pr * 2 + 0], alo[mt], bh + 0);
                    MMA8(C[mt][pr * 2 + 0], ahi[mt], bl + 0);
                    MMA8(C[mt][pr * 2 + 1], ahi[mt], bh + 2);
                    MMA8(C[mt][pr * 2 + 1], alo[mt], bh + 2);
                    MMA8(C[mt][pr * 2 + 1], ahi[mt], bl + 2);
                }
            }
        }
        __syncthreads();
    }

    // Epilogue
    const float* __restrict__ bias1 = g_sel.b1;
    const float* __restrict__ bias2 = g_sel.b2;
#pragma unroll
    for (int mt = 0; mt < 2; mt++) {
        int gr0 = rowTile + wm * 32 + mt * 16 + (lane >> 2);
#pragma unroll
        for (int nt = 0; nt < 8; nt++) {
            int lc = wn * 64 + nt * 8 + (lane & 3) * 2;
#pragma unroll
            for (int h = 0; h < 2; h++) {
                int gr = gr0 + h * 8;
                if (gr >= NN) continue;
                float v0 = C[mt][nt][h * 2 + 0];
                float v1 = C[mt][nt][h * 2 + 1];
                if (IS_L1) {
                    if (by == 0) {
                        *(float2*)&g_t1[(size_t)gr * 128 + lc] = make_float2(v0, v1);
                    } else {
                        *(float2*)&g_h[(size_t)gr * 128 + lc] =
                            make_float2(v0 + bias1[lc], v1 + bias1[lc + 1]);
                    }
                } else {
                    if (lc < 64) {
                        *(float2*)&g_t2[(size_t)gr * 64 + lc] = make_float2(v0, v1);
                    } else {
                        *(float2*)&out2[(size_t)gr * 64 + lc - 64] =
                            make_float2(v0 + bias2[lc - 64], v1 + bias2[lc - 63]);
                    }
                }
            }
        }
    }
}

// ---------------- gather aggregation (CSR) -----------------------------------
__global__ __launch_bounds__(256) void gather128_kernel() {
    int node = (blockIdx.x * blockDim.x + threadIdx.x) >> 5;
    int lane = threadIdx.x & 31;
    if (node >= NN) return;
    int beg = __ldg(g_off + node), end = __ldg(g_off + node + 1);
    float* row = g_h + (size_t)node * 128 + lane * 4;
    float4 acc = *(float4*)row;
    int e = beg;
    for (; e + 1 < end; e += 2) {
        int s0 = __ldg(g_eidx + e);
        int s1 = __ldg(g_eidx + e + 1);
        float4 v0 = *(const float4*)(g_t1 + (size_t)s0 * 128 + lane * 4);
        float4 v1 = *(const float4*)(g_t1 + (size_t)s1 * 128 + lane * 4);
        acc.x += v0.x + v1.x; acc.y += v0.y + v1.y;
        acc.z += v0.z + v1.z; acc.w += v0.w + v1.w;
    }
    if (e < end) {
        int s0 = __ldg(g_eidx + e);
        float4 v0 = *(const float4*)(g_t1 + (size_t)s0 * 128 + lane * 4);
        acc.x += v0.x; acc.y += v0.y; acc.z += v0.z; acc.w += v0.w;
    }
    acc.x = fmaxf(acc.x, 0.f); acc.y = fmaxf(acc.y, 0.f);
    acc.z = fmaxf(acc.z, 0.f); acc.w = fmaxf(acc.w, 0.f);
    *(float4*)row = acc;
}

__global__ __launch_bounds__(256) void gather64_kernel(float* __restrict__ out) {
    int node = (blockIdx.x * blockDim.x + threadIdx.x) >> 5;
    int lane = threadIdx.x & 31;
    if (node >= NN) return;
    int beg = __ldg(g_off + node), end = __ldg(g_off + node + 1);
    float* row = out + (size_t)node * 64 + lane * 2;
    float2 acc = *(float2*)row;
    int e = beg;
    for (; e + 1 < end; e += 2) {
        int s0 = __ldg(g_eidx + e);
        int s1 = __ldg(g_eidx + e + 1);
        float2 v0 = *(const float2*)(g_t2 + (size_t)s0 * 64 + lane * 2);
        float2 v1 = *(const float2*)(g_t2 + (size_t)s1 * 64 + lane * 2);
        acc.x += v0.x + v1.x; acc.y += v0.y + v1.y;
    }
    if (e < end) {
        int s0 = __ldg(g_eidx + e);
        float2 v0 = *(const float2*)(g_t2 + (size_t)s0 * 64 + lane * 2);
        acc.x += v0.x; acc.y += v0.y;
    }
    *(float2*)row = acc;
}

// ---------------- launch ----------------------------------------------------
extern "C" void kernel_launch(void* const* d_in, const int* in_sizes, int n_in,
                              void* d_out, int out_size) {
    Cands c;
    c.nx = c.ne = c.n1 = c.n2 = c.nb1 = c.nb2 = 0;
    for (int i = 0; i < MAXC; i++) {
        c.xc[i] = nullptr; c.ec[i] = nullptr; c.w1c[i] = nullptr;
        c.w2c[i] = nullptr; c.b1c[i] = nullptr; c.b2c[i] = nullptr;
    }
    for (int i = 0; i < n_in; i++) {
        switch (in_sizes[i]) {
            case 12800000: if (c.nx  < MAXC) c.xc [c.nx++ ] = (const float*)d_in[i]; break;
            case 6400000:  if (c.ne  < MAXC) c.ec [c.ne++ ] = d_in[i]; break;
            case 16384:    if (c.n1  < MAXC) c.w1c[c.n1++ ] = (const float*)d_in[i]; break;
            case 8192:     if (c.n2  < MAXC) c.w2c[c.n2++ ] = (const float*)d_in[i]; break;
            case 128:      if (c.nb1 < MAXC) c.b1c[c.nb1++] = (const float*)d_in[i]; break;
            case 64:       if (c.nb2 < MAXC) c.b2c[c.nb2++] = (const float*)d_in[i]; break;
            default: break;
        }
    }
    float* out = (float*)d_out;

    // Opt in to 64KB dynamic smem for the pipelined MMA kernels.
    cudaFuncSetAttribute(mma_dual<true>,  cudaFuncAttributeMaxDynamicSharedMemorySize, SMEM_TOTAL_MMA);
    cudaFuncSetAttribute(mma_dual<false>, cudaFuncAttributeMaxDynamicSharedMemorySize, SMEM_TOTAL_MMA);

    cudaStream_t sB;
    cudaStreamCreateWithFlags(&sB, cudaStreamNonBlocking);
    cudaEvent_t evFork, evJoin;
    cudaEventCreateWithFlags(&evFork, cudaEventDisableTiming);
    cudaEventCreateWithFlags(&evJoin, cudaEventDisableTiming);

    probe_kernel<<<1, 32>>>(c);
    cudaEventRecord(evFork, 0);
    cudaStreamWaitEvent(sB, evFork, 0);

    // Branch B: CSR build
    zero_kernel<<<(NN + 255) / 256, 256, 0, sB>>>();
    hist_kernel<<<(EE + 255) / 256, 256, 0, sB>>>();
    scan1_kernel<<<SCAN_BLKS, 1024, 0, sB>>>();
    scan2_kernel<<<1, 32, 0, sB>>>();
    scan3_kernel<<<(NN + 255) / 256, 256, 0, sB>>>();
    fill_kernel<<<(EE + 255) / 256, 256, 0, sB>>>();
    cudaEventRecord(evJoin, sB);

    // Branch A: layer-1 GEMM (tf32 tensor cores, 3xTF32, pipelined)
    const int rowBlocks = (NN + 127) / 128;  // 782
    mma_dual<true><<<dim3(rowBlocks, 2), 256, SMEM_TOTAL_MMA>>>(nullptr);

    cudaStreamWaitEvent(0, evJoin, 0);
    gather128_kernel<<<(NN * 32 + 255) / 256, 256>>>();

    mma_dual<false><<<dim3(rowBlocks, 1), 256, SMEM_TOTAL_MMA>>>(out);

    gather64_kernel<<<(NN * 32 + 255) / 256, 256>>>(out);
}